// round 8
// baseline (speedup 1.0000x reference)
#include <cuda_runtime.h>
#include <cuda_bf16.h>
#include <cstdint>

typedef __nv_bfloat16 bf16;

#define NB 32
#define TT 64
#define NSTEP 63
#define HH 1024
#define VV 32000
#define GRID_P 128

// swizzle for 1024-byte-stride rows (32x512 bf16 chunks)
__device__ __forceinline__ uint32_t SWZ(uint32_t off) {
    return off ^ (((off >> 10) & 7u) << 4);
}

// ---------------- static scratch --------------------------------------------
__device__ __align__(128) bf16 g_W0q[4096 * 2048];  // 128 tiles x 4 q x 32KB, SWZ
__device__ __align__(128) bf16 g_W1q[4096 * 2048];
__device__ __align__(128) bf16 g_Wlzq[1024 * 1024]; // 32 tiles x 2 q x 32KB, SWZ
__device__ __align__(128) bf16 g_W0e[4096 * 512];   // interleaved rows, linear
__device__ __align__(128) bf16 g_WaT[1024 * 1024];
__device__ __align__(128) bf16 g_Wlc[1024 * 1024];
__device__ __align__(128) bf16 g_Wg [32000 * 1024];
__device__ __align__(128) bf16 g_eseq[2048 * 512];
__device__ __align__(128) float g_eg [2048 * 4096]; // e@W0e^T + b0 (interleaved cols)
__device__ __align__(128) bf16 g_xe[2048 * 1024];
__device__ __align__(128) bf16 g_xa[2048 * 1024];
__device__ __align__(128) bf16 g_xc[2048 * 1024];
__device__ __align__(128) bf16 g_outs[2048 * 1024]; // linear rows t*32+b (2016 used)
__device__ float g_b1i[4096];
__device__ float g_b0i[4096];
__device__ __align__(128) bf16 g_h0buf[2 * NB * HH]; // two 64KB chunked+SWZ bufs
__device__ __align__(128) bf16 g_h1buf[2 * NB * HH];
__device__ float g_c0[NB * HH];
__device__ float g_c1[NB * HH];
__device__ float g_ctxl[NB * HH];
__device__ float g_wl[NB * HH];
__device__ float g_badot[2048];
__device__ unsigned long long g_bar_cnt;
__device__ unsigned long long g_bar_gen;

// ---------------- helpers ----------------------------------------------------
__device__ __forceinline__ uint32_t smem_u32(const void* p) {
    return (uint32_t)__cvta_generic_to_shared(p);
}
__device__ __forceinline__ void ldsm4(uint32_t addr, uint32_t& r0, uint32_t& r1,
                                      uint32_t& r2, uint32_t& r3) {
    asm volatile("ldmatrix.sync.aligned.m8n8.x4.shared.b16 {%0,%1,%2,%3}, [%4];"
                 : "=r"(r0), "=r"(r1), "=r"(r2), "=r"(r3) : "r"(addr));
}
__device__ __forceinline__ void mma16816(float* c, uint32_t a0, uint32_t a1,
                                         uint32_t a2, uint32_t a3,
                                         uint32_t b0, uint32_t b1) {
    asm volatile(
        "mma.sync.aligned.m16n8k16.row.col.f32.bf16.bf16.f32 "
        "{%0,%1,%2,%3},{%4,%5,%6,%7},{%8,%9},{%0,%1,%2,%3};"
        : "+f"(c[0]), "+f"(c[1]), "+f"(c[2]), "+f"(c[3])
        : "r"(a0), "r"(a1), "r"(a2), "r"(a3), "r"(b0), "r"(b1));
}
__device__ __forceinline__ float sigmoidf_(float x) { return 1.f / (1.f + expf(-x)); }
__device__ __forceinline__ uint4 pack8(float4 a, float4 b) {
    uint4 o;
    __nv_bfloat162 p;
    p = __floats2bfloat162_rn(a.x, a.y); o.x = *(uint32_t*)&p;
    p = __floats2bfloat162_rn(a.z, a.w); o.y = *(uint32_t*)&p;
    p = __floats2bfloat162_rn(b.x, b.y); o.z = *(uint32_t*)&p;
    p = __floats2bfloat162_rn(b.z, b.w); o.w = *(uint32_t*)&p;
    return o;
}
// --- 1D TMA bulk + mbarrier ---
__device__ __forceinline__ void tma1d(uint32_t dst, const void* src, uint32_t bytes,
                                      uint32_t mbar) {
    asm volatile(
        "cp.async.bulk.shared::cluster.global.mbarrier::complete_tx::bytes "
        "[%0], [%1], %2, [%3];"
        :: "r"(dst), "l"(src), "r"(bytes), "r"(mbar) : "memory");
}
__device__ __forceinline__ void mb_init(uint32_t mbar) {
    asm volatile("mbarrier.init.shared.b64 [%0], 1;" :: "r"(mbar) : "memory");
}
__device__ __forceinline__ void mb_expect(uint32_t mbar, uint32_t tx) {
    asm volatile("mbarrier.arrive.expect_tx.shared.b64 _, [%0], %1;"
                 :: "r"(mbar), "r"(tx) : "memory");
}
__device__ __forceinline__ void mb_wait(uint32_t mbar, int parity) {
    asm volatile(
        "{\n\t.reg .pred P;\n"
        "WL%=:\n\t"
        "mbarrier.try_wait.parity.acquire.cta.shared::cta.b64 P, [%0], %1, 0x989680;\n\t"
        "@P bra WD%=;\n\t"
        "bra WL%=;\n"
        "WD%=:\n\t}"
        :: "r"(mbar), "r"(parity) : "memory");
}
// grid-wide barrier (monotonic counter, graph-replay safe)
__device__ __forceinline__ void gbar() {
    __syncthreads();
    if (threadIdx.x == 0) {
        __threadfence();
        unsigned long long arrive = atomicAdd(&g_bar_cnt, 1ULL);
        unsigned long long target = arrive / GRID_P + 1ULL;
        if ((arrive % GRID_P) == GRID_P - 1) {
            atomicAdd(&g_bar_gen, 1ULL);
        } else {
            unsigned long long g;
            do {
                __nanosleep(32);
                asm volatile("ld.acquire.gpu.global.u64 %0, [%1];"
                             : "=l"(g) : "l"(&g_bar_gen));
            } while (g < target);
        }
        __threadfence();
    }
    __syncthreads();
}

// ---------------- conversion kernels ----------------------------------------
__global__ void k_cvt8(bf16* dst, const float* src, int n8) {
    int i = blockIdx.x * blockDim.x + threadIdx.x;
    if (i < n8) {
        const float4* s = (const float4*)src + (size_t)i * 2;
        ((uint4*)dst)[i] = pack8(s[0], s[1]);
    }
}
__global__ void k_cvt_wq(bf16* dst, const float* Wih, int ihStride, int ihOff,
                         const float* Whh) {
    int i = blockIdx.x * blockDim.x + threadIdx.x;   // 4096*256
    if (i >= 4096 * 256) return;
    int rn = i >> 8, c = (i & 255) * 8;
    int srow = (rn & 3) * 1024 + (rn >> 2);
    const float* s = (c < 1024) ? (Wih + (size_t)srow * ihStride + ihOff + c)
                                : (Whh + (size_t)srow * 1024 + (c - 1024));
    uint32_t off = SWZ((uint32_t)((rn & 31) * 1024 + (c & 511) * 2));
    char* d = (char*)dst + (size_t)(rn >> 5) * 131072 + (size_t)(c >> 9) * 32768 + off;
    *(uint4*)d = pack8(((const float4*)s)[0], ((const float4*)s)[1]);
}
__global__ void k_cvt_wlzq(bf16* dst, const float* Wl) {
    int i = blockIdx.x * blockDim.x + threadIdx.x;   // 1024*128
    if (i >= 1024 * 128) return;
    int rn = i >> 7, c = (i & 127) * 8;
    const float* s = Wl + (size_t)rn * 2048 + c;
    uint32_t off = SWZ((uint32_t)((rn & 31) * 1024 + (c & 511) * 2));
    char* d = (char*)dst + (size_t)(rn >> 5) * 65536 + (size_t)(c >> 9) * 32768 + off;
    *(uint4*)d = pack8(((const float4*)s)[0], ((const float4*)s)[1]);
}
__global__ void k_cvt_w0e_i8(bf16* dst, const float* Wih0) {
    int i = blockIdx.x * blockDim.x + threadIdx.x;   // 4096*64
    if (i < 4096 * 64) {
        int rn = i >> 6, c8 = (i & 63) * 8;
        int srow = (rn & 3) * 1024 + (rn >> 2);
        const float* s = Wih0 + (size_t)srow * 1536 + c8;
        ((uint4*)dst)[i] = pack8(((const float4*)s)[0], ((const float4*)s)[1]);
    }
}
__global__ void k_cvt_slice8(bf16* dst, const float* src, int strideS, int off,
                             int w8, int n8) {
    int i = blockIdx.x * blockDim.x + threadIdx.x;
    if (i < n8) {
        int r = i / w8, c8 = (i % w8) * 8;
        const float* s = src + (size_t)r * strideS + off + c8;
        ((uint4*)dst)[i] = pack8(((const float4*)s)[0], ((const float4*)s)[1]);
    }
}
__global__ void k_cvt_T(bf16* dst, const float* src) {
    int i = blockIdx.x * blockDim.x + threadIdx.x;
    if (i < 1024 * 1024) {
        int n = i >> 10, h = i & 1023;
        dst[i] = __float2bfloat16(src[h * 1024 + n]);
    }
}
__global__ void k_addb_i(float* dst, const float* a, const float* b) {
    int i = blockIdx.x * blockDim.x + threadIdx.x;
    if (i < 4096) {
        int u = i >> 2, g = i & 3;
        dst[i] = a[g * 1024 + u] + b[g * 1024 + u];
    }
}
__global__ void k_embed8(bf16* eseq, const int* x, const float* emb) {
    int i = blockIdx.x * blockDim.x + threadIdx.x;
    if (i < NSTEP * NB * 64) {
        int c8 = (i & 63) * 8;
        int m = i >> 6;
        int b = m & 31, t = m >> 5;
        int tok = x[b * TT + t];
        const float* s = emb + (size_t)tok * 512 + c8;
        ((uint4*)eseq)[i] = pack8(((const float4*)s)[0], ((const float4*)s)[1]);
    }
}
__global__ void k_init(const float* h0in, const float* c0in) {
    int i = blockIdx.x * blockDim.x + threadIdx.x;
    if (i < NB * HH) {
        int b = i >> 10, u = i & 1023;
        uint32_t off = (uint32_t)(u >> 9) * 32768 + SWZ((uint32_t)(b * 1024 + (u & 511) * 2));
        *(bf16*)((char*)g_h0buf + off) = __float2bfloat16(h0in[i]);
        *(bf16*)((char*)g_h1buf + off) = __float2bfloat16(h0in[NB * HH + i]);
        g_c0[i] = c0in[i];
        g_c1[i] = c0in[NB * HH + i];
    }
}
__global__ void k_badot(const float* ba, const float* x_enc, float* badot) {
    int warp = threadIdx.x >> 5, lane = threadIdx.x & 31;
    int row = blockIdx.x * 8 + warp;
    const float* xr = x_enc + (size_t)row * 1024;
    float s = 0.f;
    for (int h = lane; h < 1024; h += 32) s += ba[h] * xr[h];
#pragma unroll
    for (int o = 16; o; o >>= 1) s += __shfl_xor_sync(0xffffffffu, s, o);
    if (lane == 0) badot[row] = s;
}

// ---------------- generic 128x128 GEMM (precompute) --------------------------
__global__ void __launch_bounds__(256) k_gemm_big(
    const bf16* __restrict__ A, const bf16* __restrict__ W,
    const float* __restrict__ bias, float* __restrict__ Cf, bf16* __restrict__ Cb,
    int N, int K, int mode)
{
    __shared__ __align__(16) bf16 As[128 * 40];
    __shared__ __align__(16) bf16 Bs[128 * 40];
    const int tid = threadIdx.x, warp = tid >> 5, lane = tid & 31;
    const int wr = warp >> 2, wc = warp & 3;
    const int mblk = blockIdx.y * 128;
    const int nblk = blockIdx.x * 128;
    const int sub = lane >> 3, ri = lane & 7;

    float acc[4][4][4];
#pragma unroll
    for (int a = 0; a < 4; a++)
#pragma unroll
        for (int b = 0; b < 4; b++)
#pragma unroll
            for (int c = 0; c < 4; c++) acc[a][b][c] = 0.f;

    for (int kb = 0; kb < K; kb += 32) {
        __syncthreads();
#pragma unroll
        for (int i = 0; i < 4; i++) {
            int v = tid + i * 256;
            if (v < 512) {
                int m = v >> 2, cv = v & 3;
                *(uint4*)&As[m * 40 + cv * 8] =
                    *(const uint4*)(A + (size_t)(mblk + m) * K + kb + cv * 8);
            } else {
                int u = v - 512;
                int n = u >> 2, cv = u & 3;
                *(uint4*)&Bs[n * 40 + cv * 8] =
                    *(const uint4*)(W + (size_t)(nblk + n) * K + kb + cv * 8);
            }
        }
        __syncthreads();
#pragma unroll
        for (int kk = 0; kk < 32; kk += 16) {
            uint32_t a[4][4], b[4][2];
#pragma unroll
            for (int mt = 0; mt < 4; mt++) {
                int row = wr * 64 + mt * 16 + (sub & 1) * 8 + ri;
                int col = kk + (sub >> 1) * 8;
                ldsm4(smem_u32(&As[row * 40 + col]), a[mt][0], a[mt][1], a[mt][2], a[mt][3]);
            }
#pragma unroll
            for (int ntp = 0; ntp < 2; ntp++) {
                int row = wc * 32 + ntp * 16 + (sub >> 1) * 8 + ri;
                int col = kk + (sub & 1) * 8;
                ldsm4(smem_u32(&Bs[row * 40 + col]),
                      b[ntp * 2][0], b[ntp * 2][1], b[ntp * 2 + 1][0], b[ntp * 2 + 1][1]);
            }
#pragma unroll
            for (int mt = 0; mt < 4; mt++)
#pragma unroll
                for (int nt = 0; nt < 4; nt++)
                    mma16816(acc[mt][nt], a[mt][0], a[mt][1], a[mt][2], a[mt][3],
                             b[nt][0], b[nt][1]);
        }
    }

    const int r0 = lane >> 2, c0 = (lane & 3) * 2;
#pragma unroll
    for (int mt = 0; mt < 4; mt++)
#pragma unroll
        for (int nt = 0; nt < 4; nt++) {
            int n = nblk + wc * 32 + nt * 8 + c0;
#pragma unroll
            for (int half = 0; half < 2; half++) {
                int m = mblk + wr * 64 + mt * 16 + r0 + half * 8;
                float v0 = acc[mt][nt][half * 2 + 0];
                float v1 = acc[mt][nt][half * 2 + 1];
                if (mode == 0) {
                    Cf[(size_t)m * N + n]     = v0 + bias[n];
                    Cf[(size_t)m * N + n + 1] = v1 + bias[n + 1];
                } else {
                    Cb[(size_t)m * N + n]     = __float2bfloat16(v0);
                    Cb[(size_t)m * N + n + 1] = __float2bfloat16(v1);
                }
            }
        }
}

// ---------------- persistent recurrence --------------------------------------
// smem: A chunks 0..3 @0/32768/65536/98304; W bufs @131072/163840;
//       red @196608 (33792B); mbars @230400 (24B)
#define SMOFF_WB0 131072
#define SMOFF_WB1 163840
#define SMOFF_RED 196608
#define SMOFF_MB  230400
#define SMEM_RECUR 230432

struct MPh { int a, w0, w1; };

__device__ __forceinline__ void comp_chunk(uint32_t aB, uint32_t wB,
                                           float acc[2][4][4]) {
    const int warp = threadIdx.x >> 5, lane = threadIdx.x & 31;
    const int sub = lane >> 3, ri = lane & 7;
#pragma unroll
    for (int kk = 0; kk < 64; kk += 16) {
        int col = (warp << 6) + kk;
        uint32_t a[2][4], b[4][2];
#pragma unroll
        for (int mt = 0; mt < 2; mt++) {
            uint32_t off = (uint32_t)((mt * 16 + (sub & 1) * 8 + ri) * 1024 +
                                      (col + (sub >> 1) * 8) * 2);
            ldsm4(aB + SWZ(off), a[mt][0], a[mt][1], a[mt][2], a[mt][3]);
        }
#pragma unroll
        for (int ntp = 0; ntp < 2; ntp++) {
            uint32_t off = (uint32_t)((ntp * 16 + (sub >> 1) * 8 + ri) * 1024 +
                                      (col + (sub & 1) * 8) * 2);
            ldsm4(wB + SWZ(off), b[ntp * 2][0], b[ntp * 2][1],
                  b[ntp * 2 + 1][0], b[ntp * 2 + 1][1]);
        }
#pragma unroll
        for (int mt = 0; mt < 2; mt++)
#pragma unroll
            for (int nt = 0; nt < 4; nt++)
                mma16816(acc[mt][nt], a[mt][0], a[mt][1], a[mt][2], a[mt][3],
                         b[nt][0], b[nt][1]);
    }
}

__device__ __forceinline__ void reduce32(char* sm, float acc[2][4][4], float out[4]) {
    float* red = (float*)(sm + SMOFF_RED);
    const int tid = threadIdx.x, warp = tid >> 5, lane = tid & 31;
    __syncthreads();
    float* rw = red + warp * (32 * 33);
#pragma unroll
    for (int mt = 0; mt < 2; mt++)
#pragma unroll
        for (int nt = 0; nt < 4; nt++) {
            int m = mt * 16 + (lane >> 2);
            int n0 = nt * 8 + (lane & 3) * 2;
            rw[m * 33 + n0]           = acc[mt][nt][0];
            rw[m * 33 + n0 + 1]       = acc[mt][nt][1];
            rw[(m + 8) * 33 + n0]     = acc[mt][nt][2];
            rw[(m + 8) * 33 + n0 + 1] = acc[mt][nt][3];
        }
    __syncthreads();
    int b = tid >> 3, ul = tid & 7;
#pragma unroll
    for (int g = 0; g < 4; g++) {
        float s = 0.f;
#pragma unroll
        for (int w = 0; w < 8; w++) s += red[w * (32 * 33) + b * 33 + ul * 4 + g];
        out[g] = s;
    }
}

// A chunks resident in smem (0..nch-1); W streamed double-buffered from wtile.
__device__ void gemm_ws(const char* wtile, int nch, char* sm, MPh& ph,
                        bool w0pre, float out[4]) {
    const int tid = threadIdx.x;
    uint32_t smb = smem_u32(sm);
    uint32_t mbA = smb + SMOFF_MB, mbW0 = mbA + 8, mbW1 = mbA + 16;
    float acc[2][4][4];
#pragma unroll
    for (int a = 0; a < 2; a++)
#pragma unroll
        for (int b = 0; b < 4; b++)
#pragma unroll
            for (int c = 0; c < 4; c++) acc[a][b][c] = 0.f;

    if (!w0pre && tid == 0) {
        mb_expect(mbW0, 32768);
        tma1d(smb + SMOFF_WB0, wtile, 32768, mbW0);
    }
    mb_wait(mbA, ph.a); ph.a ^= 1;     // all A chunks (TMA'd ones)
    for (int ch = 0; ch < nch; ch++) {
        int buf = ch & 1;
        if (ch + 1 < nch && tid == 0) {
            uint32_t mbn = buf ? mbW0 : mbW1;
            mb_expect(mbn, 32768);
            tma1d(smb + (buf ? SMOFF_WB0 : SMOFF_WB1),
                  wtile + (size_t)(ch + 1) * 32768, 32768, mbn);
        }
        if (buf) { mb_wait(mbW1, ph.w1); ph.w1 ^= 1; }
        else     { mb_wait(mbW0, ph.w0); ph.w0 ^= 1; }
        comp_chunk(smb + (uint32_t)ch * 32768,
                   smb + (buf ? SMOFF_WB1 : SMOFF_WB0), acc);
        __syncthreads();
    }
    reduce32(sm, acc, out);
}

// ---------------- attention (device func) ------------------------------------
__device__ void attn_dev(int b, const char* __restrict__ h1base, char* smraw) {
    float* h1s = (float*)(smraw + SMOFF_RED);
    float* sc = h1s + 1024;
    int tid = threadIdx.x;
    for (int u = tid; u < 1024; u += 256) {
        uint32_t off = (uint32_t)(u >> 9) * 32768 + SWZ((uint32_t)(b * 1024 + (u & 511) * 2));
        h1s[u] = __bfloat162float(*(const bf16*)(h1base + off));
    }
    __syncthreads();
    int warp = tid >> 5, lane = tid & 31;
#pragma unroll
    for (int jj = 0; jj < 8; jj++) {
        int j = warp * 8 + jj;
        const uint4* xr = (const uint4*)(g_xa + (size_t)(b * 64 + j) * 1024);
        float s = 0.f;
        for (int k4 = lane; k4 < 128; k4 += 32) {
            uint4 v = xr[k4];
            const __nv_bfloat162* p2 = (const __nv_bfloat162*)&v;
            int base = k4 * 8;
#pragma unroll
            for (int q = 0; q < 4; q++) {
                float2 f = __bfloat1622float2(p2[q]);
                s += h1s[base + q * 2] * f.x + h1s[base + q * 2 + 1] * f.y;
            }
        }
#pragma unroll
        for (int o = 16; o; o >>= 1) s += __shfl_xor_sync(0xffffffffu, s, o);
        if (lane == 0) sc[j] = s + g_badot[b * 64 + j];
    }
    __syncthreads();
    if (warp == 0) {
        float v0 = sc[lane], v1 = sc[lane + 32];
        float m = fmaxf(v0, v1);
#pragma unroll
        for (int o = 16; o; o >>= 1) m = fmaxf(m, __shfl_xor_sync(0xffffffffu, m, o));
        float e0 = expf(v0 - m), e1 = expf(v1 - m);
        float s = e0 + e1;
#pragma unroll
        for (int o = 16; o; o >>= 1) s += __shfl_xor_sync(0xffffffffu, s, o);
        sc[lane] = e0 / s;
        sc[lane + 32] = e1 / s;
    }
    __syncthreads();
    // ctx: 4 cols per thread, 8B loads
    {
        int n0 = tid * 4;
        float a0 = 0.f, a1 = 0.f, a2 = 0.f, a3 = 0.f;
        const char* base = (const char*)g_xc + (size_t)b * 131072 + n0 * 2;
#pragma unroll 8
        for (int j = 0; j < 64; j++) {
            uint2 v = *(const uint2*)(base + (size_t)j * 2048);
            float2 f0 = __bfloat1622float2(*(__nv_bfloat162*)&v.x);
            float2 f1 = __bfloat1622float2(*(__nv_bfloat162*)&v.y);
            float w = sc[j];
            a0 += w * f0.x; a1 += w * f0.y; a2 += w * f1.x; a3 += w * f1.y;
        }
        *(float4*)&g_ctxl[b * 1024 + n0] = make_float4(a0, a1, a2, a3);
    }
}

// ---------------- persistent recurrence kernel -------------------------------
__global__ void __launch_bounds__(256) k_recur(const float* __restrict__ bl) {
    extern __shared__ __align__(128) char smraw[];
    const int bid = blockIdx.x;
    const int tid = threadIdx.x;
    uint32_t smb = smem_u32(smraw);
    uint32_t mbA = smb + SMOFF_MB;

    if (tid == 0) { mb_init(mbA); mb_init(mbA + 8); mb_init(mbA + 16); }
    asm volatile("fence.proxy.async.shared::cta;" ::: "memory");
    __syncthreads();
    MPh ph; ph.a = 0; ph.w0 = 0; ph.w1 = 0;

    for (int t = 0; t < NSTEP; t++) {
        const char* h0_in  = (const char*)g_h0buf + (t & 1) * 65536;
        char*       h0_out = (char*)g_h0buf + ((t + 1) & 1) * 65536;
        const char* h1_in  = (const char*)g_h1buf + (t & 1) * 65536;
        char*       h1_out = (char*)g_h1buf + ((t + 1) & 1) * 65536;

        // ---- P1: build out_{t-1} into A0/A1, TMA h0_in into A2/A3 + W stream
        if (bid < 128) {
            if (tid == 0) {
                mb_expect(mbA, 65536);
                tma1d(smb + 65536, h0_in, 32768, mbA);
                tma1d(smb + 98304, h0_in + 32768, 32768, mbA);
                mb_expect(mbA + 8, 32768);
                tma1d(smb + SMOFF_WB0, (const char*)g_W0q + (size_t)bid * 131072,
                      32768, mbA + 8);
            }
            // build out tile (32 x 1024 bf16, swizzled) into A0/A1
            {
                int b = tid >> 3, u0 = (tid & 7) * 128;
                const float* wlb = g_wl + b * 1024;
                const float* ctb = g_ctxl + b * 1024;
#pragma unroll
                for (int j = 0; j < 128; j += 8) {
                    int u = u0 + j;
                    uint4 pk;
                    if (t == 0) {
                        pk = make_uint4(0u, 0u, 0u, 0u);
                    } else {
                        float4 wa = *(const float4*)(wlb + u);
                        float4 wb = *(const float4*)(wlb + u + 4);
                        float4 ca = *(const float4*)(ctb + u);
                        float4 cb = *(const float4*)(ctb + u + 4);
                        float4 b1 = *(const float4*)(bl + u);
                        float4 b2 = *(const float4*)(bl + u + 4);
                        float4 r1 = make_float4(tanhf(wa.x + ca.x + b1.x),
                                                tanhf(wa.y + ca.y + b1.y),
                                                tanhf(wa.z + ca.z + b1.z),
                                                tanhf(wa.w + ca.w + b1.w));
                        float4 r2 = make_float4(tanhf(wb.x + cb.x + b2.x),
                                                tanhf(wb.y + cb.y + b2.y),
                                                tanhf(wb.z + cb.z + b2.z),
                                                tanhf(wb.w + cb.w + b2.w));
                        pk = pack8(r1, r2);
                    }
                    *(uint4*)(smraw + ((u >> 9) * 32768) +
                              SWZ((uint32_t)(b * 1024 + (u & 511) * 2))) = pk;
                }
                if (bid < 32 && t > 0) {   // materialize out row for generator
                    int n = tid * 4;
                    bf16* dst = g_outs + (size_t)((t - 1) * 32 + bid) * 1024 + n;
#pragma unroll
                    for (int k = 0; k < 4; k++) {
                        float v = g_wl[bid * 1024 + n + k] + g_ctxl[bid * 1024 + n + k]
                                  + bl[n + k];
                        dst[k] = __float2bfloat16(tanhf(v));
                    }
                }
            }
            __syncthreads();
            float s[4];
            gemm_ws((const char*)g_W0q + (size_t)bid * 131072, 4, smraw, ph, true, s);
            const float* egp = g_eg + (size_t)t * 32 * 4096;
            int b = tid >> 3, ul = tid & 7;
            int rn = bid * 32 + ul * 4;
            int u = rn >> 2;
            float ig = s[0] + egp[b * 4096 + rn];
            float fg = s[1] + egp[b * 4096 + rn + 1];
            float gg = s[2] + egp[b * 4096 + rn + 2];
            float og = s[3] + egp[b * 4096 + rn + 3];
            float cn = sigmoidf_(fg) * g_c0[b * 1024 + u] + sigmoidf_(ig) * tanhf(gg);
            g_c0[b * 1024 + u] = cn;
            uint32_t off = (uint32_t)(u >> 9) * 32768 +
                           SWZ((uint32_t)(b * 1024 + (u & 511) * 2));
            *(bf16*)(h0_out + off) = __float2bfloat16(sigmoidf_(og) * tanhf(cn));
        }
        gbar();

        // ---- P2: gates1 = [h0_new | h1_prev] @ W1^T
        if (bid < 128) {
            if (tid == 0) {
                mb_expect(mbA, 131072);
                tma1d(smb + 0,     h0_out, 32768, mbA);
                tma1d(smb + 32768, h0_out + 32768, 32768, mbA);
                tma1d(smb + 65536, h1_in, 32768, mbA);
                tma1d(smb + 98304, h1_in + 32768, 32768, mbA);
            }
            float s[4];
            gemm_ws((const char*)g_W1q + (size_t)bid * 131072, 4, smraw, ph, false, s);
            int b = tid >> 3, ul = tid & 7;
            int rn = bid * 32 + ul * 4;
            int u = rn >> 2;
            float ig = s[0] + g_b1i[rn];
            float fg = s[1] + g_b1i[rn + 1];
            float gg = s[2] + g_b1i[rn + 2];
            float og = s[3] + g_b1i[rn + 3];
            float cn = sigmoidf_(fg) * g_c1[b * 1024 + u] + sigmoidf_(ig) * tanhf(gg);
            g_c1[b * 1024 + u] = cn;
            uint32_t off = (uint32_t)(u >> 9) * 32768 +
                           SWZ((uint32_t)(b * 1024 + (u & 511) * 2));
            *(bf16*)(h1_out + off) = __float2bfloat16(sigmoidf_(og) * tanhf(cn));
        }
        gbar();

        // ---- P3: attention (0-31) || wl = z @ Wlz^T (32-63)
        if (bid < 32) {
            attn_dev(bid, h1_out, smraw);
        } else if (bid < 64) {
            if (tid == 0) {
                mb_expect(mbA, 65536);
                tma1d(smb + 0,     h1_out, 32768, mbA);
                tma1d(smb + 32768, h1_out + 32768, 32768, mbA);
            }
            float s[4];
            gemm_ws((const char*)g_Wlzq + (size_t)(bid - 32) * 65536, 2, smraw, ph,
                    false, s);
            int b = tid >> 3, ul = tid & 7;
            int n = (bid - 32) * 32 + ul * 4;
#pragma unroll
            for (int g = 0; g < 4; g++) g_wl[b * 1024 + n + g] = s[g];
        }
        gbar();
    }

    // final out row (t = 62) for the generator
    if (bid < 32) {
        int n = tid * 4;
        bf16* dst = g_outs + (size_t)(62 * 32 + bid) * 1024 + n;
#pragma unroll
        for (int k = 0; k < 4; k++) {
            float v = g_wl[bid * 1024 + n + k] + g_ctxl[bid * 1024 + n + k] + bl[n + k];
            dst[k] = __float2bfloat16(tanhf(v));
        }
    }
}

// ---------------- generator GEMM 256x128 tiles (linear A) ---------------------
__global__ void __launch_bounds__(256) k_gen(const bf16* __restrict__ A,
                                             const bf16* __restrict__ W,
                                             const float* __restrict__ bias,
                                             float* __restrict__ out) {
    __shared__ __align__(16) bf16 As[256 * 40];
    __shared__ __align__(16) bf16 Ws[128 * 40];
    const int tid = threadIdx.x, warp = tid >> 5, lane = tid & 31;
    const int wr = warp >> 1, wc = warp & 1;
    const int mblk = blockIdx.y * 256;
    const int nblk = blockIdx.x * 128;
    const int sub = lane >> 3, ri = lane & 7;

    float acc[4][8][4];
#pragma unroll
    for (int a = 0; a < 4; a++)
#pragma unroll
        for (int b = 0; b < 8; b++)
#pragma unroll
            for (int c = 0; c < 4; c++) acc[a][b][c] = 0.f;

    for (int kb = 0; kb < 1024; kb += 32) {
        __syncthreads();
#pragma unroll
        for (int i = 0; i < 6; i++) {
            int v = tid + i * 256;
            if (v < 1024) {
                int m = v >> 2, cv = v & 3;
                *(uint4*)&As[m * 40 + cv * 8] =
                    *(const uint4*)(A + (size_t)(mblk + m) * 1024 + kb + cv * 8);
            } else {
                int u = v - 1024;
                int n = u >> 2, cv = u & 3;
                *(uint4*)&Ws[n * 40 + cv * 8] =
                    *(const uint4*)(W + (size_t)(nblk + n) * 1024 + kb + cv * 8);
            }
        }
        __syncthreads();
#pragma unroll
        for (int kk = 0; kk < 32; kk += 16) {
            uint32_t a[4][4], b[8][2];
#pragma unroll
            for (int mt = 0; mt < 4; mt++) {
                int row = wr * 64 + mt * 16 + (sub & 1) * 8 + ri;
                int col = kk + (sub >> 1) * 8;
                ldsm4(smem_u32(&As[row * 40 + col]), a[mt][0], a[mt][1], a[mt][2], a[mt][3]);
            }
#pragma unroll
            for (int ntp = 0; ntp < 4; ntp++) {
                int row = wc * 64 + ntp * 16 + (sub >> 1) * 8 + ri;
                int col = kk + (sub & 1) * 8;
                ldsm4(smem_u32(&Ws[row * 40 + col]),
                      b[ntp * 2][0], b[ntp * 2][1], b[ntp * 2 + 1][0], b[ntp * 2 + 1][1]);
            }
#pragma unroll
            for (int mt = 0; mt < 4; mt++)
#pragma unroll
                for (int nt = 0; nt < 8; nt++)
                    mma16816(acc[mt][nt], a[mt][0], a[mt][1], a[mt][2], a[mt][3],
                             b[nt][0], b[nt][1]);
        }
    }

    const int r0 = lane >> 2, c0 = (lane & 3) * 2;
#pragma unroll
    for (int mt = 0; mt < 4; mt++)
#pragma unroll
        for (int nt = 0; nt < 8; nt++) {
            int n = nblk + wc * 64 + nt * 8 + c0;
            float bv0 = bias[n], bv1 = bias[n + 1];
#pragma unroll
            for (int half = 0; half < 2; half++) {
                int m = mblk + wr * 64 + mt * 16 + r0 + half * 8;
                if (m < NSTEP * NB) {
                    int t = m >> 5, bb = m & 31;
                    size_t orow = (size_t)(bb * NSTEP + t) * VV;
                    out[orow + n]     = acc[mt][nt][half * 2 + 0] + bv0;
                    out[orow + n + 1] = acc[mt][nt][half * 2 + 1] + bv1;
                }
            }
        }
}

// ---------------- log_softmax: online 2-pass ----------------------------------
__global__ void __launch_bounds__(256) k_lsm(float* __restrict__ out) {
    int row = blockIdx.x;
    float4* p = (float4*)(out + (size_t)row * VV);
    __shared__ float sm_m[256];
    __shared__ float sm_s[256];
    int tid = threadIdx.x;
    float m = -1e30f, s = 0.f;
    for (int i = tid; i < 8000; i += 256) {
        float4 v = p[i];
        float x[4] = {v.x, v.y, v.z, v.w};
#pragma unroll
        for (int k = 0; k < 4; k++) {
            float nm = fmaxf(m, x[k]);
            s = s * __expf(m - nm) + __expf(x[k] - nm);
            m = nm;
        }
    }
    sm_m[tid] = m; sm_s[tid] = s;
    __syncthreads();
    for (int st = 128; st; st >>= 1) {
        if (tid < st) {
            float m2 = sm_m[tid + st], s2 = sm_s[tid + st];
            float nm = fmaxf(sm_m[tid], m2);
            sm_s[tid] = sm_s[tid] * __expf(sm_m[tid] - nm) + s2 * __expf(m2 - nm);
            sm_m[tid] = nm;
        }
        __syncthreads();
    }
    float lse = sm_m[0] + logf(sm_s[0]);
    for (int i = tid; i < 8000; i += 256) {
        float4 v = p[i];
        v.x -= lse; v.y -= lse; v.z -= lse; v.w -= lse;
        p[i] = v;
    }
}

// ---------------- host ---------------------------------------------------------
static void* sym(const void* s) {
    void* p = nullptr;
    cudaGetSymbolAddress(&p, s);
    return p;
}

extern "C" void kernel_launch(void* const* d_in, const int* in_sizes, int n_in,
                              void* d_out, int out_size) {
    const int*   x     = (const int*)d_in[0];
    const float* h0in  = (const float*)d_in[1];
    const float* c0in  = (const float*)d_in[2];
    const float* x_enc = (const float*)d_in[3];
    const float* emb   = (const float*)d_in[4];
    const float* Wih0  = (const float*)d_in[5];
    const float* Whh0  = (const float*)d_in[6];
    const float* bih0  = (const float*)d_in[7];
    const float* bhh0  = (const float*)d_in[8];
    const float* Wih1  = (const float*)d_in[9];
    const float* Whh1  = (const float*)d_in[10];
    const float* bih1  = (const float*)d_in[11];
    const float* bhh1  = (const float*)d_in[12];
    const float* Wa    = (const float*)d_in[13];
    const float* ba    = (const float*)d_in[14];
    const float* Wl    = (const float*)d_in[15];
    const float* bl    = (const float*)d_in[16];
    const float* Wg    = (const float*)d_in[17];
    const float* bg    = (const float*)d_in[18];
    float* out = (float*)d_out;

    bf16*  pW0q = (bf16*)sym(g_W0q);
    bf16*  pW1q = (bf16*)sym(g_W1q);
    bf16*  pWlzq= (bf16*)sym(g_Wlzq);
    bf16*  pW0e = (bf16*)sym(g_W0e);
    bf16*  pWaT = (bf16*)sym(g_WaT);
    bf16*  pWlc = (bf16*)sym(g_Wlc);
    bf16*  pWg  = (bf16*)sym(g_Wg);
    bf16*  pEs  = (bf16*)sym(g_eseq);
    float* pEg  = (float*)sym(g_eg);
    bf16*  pXe  = (bf16*)sym(g_xe);
    bf16*  pXa  = (bf16*)sym(g_xa);
    bf16*  pXc  = (bf16*)sym(g_xc);
    bf16*  pOuts= (bf16*)sym(g_outs);
    float* pB0i = (float*)sym(g_b0i);
    float* pB1i = (float*)sym(g_b1i);
    float* pBad = (float*)sym(g_badot);

    static bool attr_done = false;
    if (!attr_done) {
        cudaFuncSetAttribute(k_recur, cudaFuncAttributeMaxDynamicSharedMemorySize,
                             SMEM_RECUR);
        attr_done = true;
    }

    // ---- precompute ----
    {
        int n;
        n = 4096 * 256; k_cvt_wq<<<(n + 255) / 256, 256>>>(pW0q, Wih0, 1536, 512, Whh0);
        n = 4096 * 256; k_cvt_wq<<<(n + 255) / 256, 256>>>(pW1q, Wih1, 1024, 0, Whh1);
        n = 1024 * 128; k_cvt_wlzq<<<(n + 255) / 256, 256>>>(pWlzq, Wl);
        n = 4096 * 64;  k_cvt_w0e_i8<<<(n + 255) / 256, 256>>>(pW0e, Wih0);
        k_cvt_T<<<4096, 256>>>(pWaT, Wa);
        n = 1024 * 128; k_cvt_slice8<<<(n + 255) / 256, 256>>>(pWlc, Wl, 2048, 1024, 128, n);
        n = 32000 * 128; k_cvt8<<<(n + 255) / 256, 256>>>(pWg, Wg, n);
        n = 2048 * 128;  k_cvt8<<<(n + 255) / 256, 256>>>(pXe, x_enc, n);
        k_addb_i<<<16, 256>>>(pB0i, bih0, bhh0);
        k_addb_i<<<16, 256>>>(pB1i, bih1, bhh1);
        n = NSTEP * NB * 64; k_embed8<<<(n + 255) / 256, 256>>>(pEs, x, emb);
        k_init<<<128, 256>>>(h0in, c0in);
        k_badot<<<256, 256>>>(ba, x_enc, pBad);
        k_gemm_big<<<dim3(32, 16), 256>>>(pEs, pW0e, pB0i, pEg, nullptr, 4096, 512, 0);
        k_gemm_big<<<dim3(8, 16), 256>>>(pXe, pWaT, nullptr, nullptr, pXa, 1024, 1024, 1);
        k_gemm_big<<<dim3(8, 16), 256>>>(pXe, pWlc, nullptr, nullptr, pXc, 1024, 1024, 1);
    }

    // ---- recurrence: ONE persistent kernel, 3 barriers/step ----
    k_recur<<<GRID_P, 256, SMEM_RECUR>>>(bl);

    // ---- generator + log_softmax ----
    k_gen<<<dim3(250, 8), 256>>>(pOuts, pWg, bg, out);
    k_lsm<<<NSTEP * NB, 256>>>(out);

    (void)in_sizes; (void)n_in; (void)out_size;
}

// round 9
// speedup vs baseline: 1.3150x; 1.3150x over previous
#include <cuda_runtime.h>
#include <cuda_bf16.h>
#include <cstdint>

typedef __nv_bfloat16 bf16;

#define NB 32
#define TT 64
#define NSTEP 63
#define HH 1024
#define VV 32000
#define GRID_P 148

// swizzle for 1024-byte-stride rows (32x512 bf16 chunks)
__device__ __forceinline__ uint32_t SWZ(uint32_t off) {
    return off ^ (((off >> 10) & 7u) << 4);
}

// ---------------- static scratch --------------------------------------------
__device__ __align__(128) bf16 g_W0q[4096 * 2048];  // 128 tiles x 4 q x 32KB, SWZ
__device__ __align__(128) bf16 g_W1q[4096 * 2048];
__device__ __align__(128) bf16 g_Wlzq[1024 * 1024]; // 32 tiles x 2 q x 32KB, SWZ
__device__ __align__(128) bf16 g_W0e[4096 * 512];   // interleaved rows, linear
__device__ __align__(128) bf16 g_WaT[1024 * 1024];
__device__ __align__(128) bf16 g_Wlc[1024 * 1024];
__device__ __align__(128) bf16 g_Wg [32000 * 1024];
__device__ __align__(128) bf16 g_eseq[2048 * 512];
__device__ __align__(128) float g_eg [2048 * 4096]; // e@W0e^T + b0 (interleaved cols)
__device__ __align__(128) bf16 g_xe[2048 * 1024];
__device__ __align__(128) bf16 g_xa[2048 * 1024];
__device__ __align__(128) bf16 g_xc[2048 * 1024];
// outs: 65 slots of 64KB; slot = 2 chunks x (32 b x 512 cols) swizzled; slot0 zeros
__device__ __align__(128) bf16 g_outs[2080 * 1024];
__device__ float g_b1i[4096];
__device__ float g_b0i[4096];
__device__ __align__(128) bf16 g_h0buf[2 * NB * HH]; // two 64KB chunked+SWZ bufs
__device__ __align__(128) bf16 g_h1buf[2 * NB * HH];
__device__ float g_c0[NB * HH];
__device__ float g_c1[NB * HH];
__device__ float g_ctxl[NB * HH];
__device__ float g_wl[NB * HH];
__device__ float g_badot[2048];
__device__ unsigned long long g_bar_cnt;
__device__ unsigned long long g_bar_gen;

// ---------------- helpers ----------------------------------------------------
__device__ __forceinline__ uint32_t smem_u32(const void* p) {
    return (uint32_t)__cvta_generic_to_shared(p);
}
__device__ __forceinline__ void ldsm4(uint32_t addr, uint32_t& r0, uint32_t& r1,
                                      uint32_t& r2, uint32_t& r3) {
    asm volatile("ldmatrix.sync.aligned.m8n8.x4.shared.b16 {%0,%1,%2,%3}, [%4];"
                 : "=r"(r0), "=r"(r1), "=r"(r2), "=r"(r3) : "r"(addr));
}
__device__ __forceinline__ void mma16816(float* c, uint32_t a0, uint32_t a1,
                                         uint32_t a2, uint32_t a3,
                                         uint32_t b0, uint32_t b1) {
    asm volatile(
        "mma.sync.aligned.m16n8k16.row.col.f32.bf16.bf16.f32 "
        "{%0,%1,%2,%3},{%4,%5,%6,%7},{%8,%9},{%0,%1,%2,%3};"
        : "+f"(c[0]), "+f"(c[1]), "+f"(c[2]), "+f"(c[3])
        : "r"(a0), "r"(a1), "r"(a2), "r"(a3), "r"(b0), "r"(b1));
}
__device__ __forceinline__ float sigmoidf_(float x) { return 1.f / (1.f + expf(-x)); }
__device__ __forceinline__ uint4 pack8(float4 a, float4 b) {
    uint4 o;
    __nv_bfloat162 p;
    p = __floats2bfloat162_rn(a.x, a.y); o.x = *(uint32_t*)&p;
    p = __floats2bfloat162_rn(a.z, a.w); o.y = *(uint32_t*)&p;
    p = __floats2bfloat162_rn(b.x, b.y); o.z = *(uint32_t*)&p;
    p = __floats2bfloat162_rn(b.z, b.w); o.w = *(uint32_t*)&p;
    return o;
}
// --- 1D TMA bulk + mbarrier ---
__device__ __forceinline__ void tma1d(uint32_t dst, const void* src, uint32_t bytes,
                                      uint32_t mbar) {
    asm volatile(
        "cp.async.bulk.shared::cluster.global.mbarrier::complete_tx::bytes "
        "[%0], [%1], %2, [%3];"
        :: "r"(dst), "l"(src), "r"(bytes), "r"(mbar) : "memory");
}
__device__ __forceinline__ void mb_init(uint32_t mbar) {
    asm volatile("mbarrier.init.shared.b64 [%0], 1;" :: "r"(mbar) : "memory");
}
__device__ __forceinline__ void mb_expect(uint32_t mbar, uint32_t tx) {
    asm volatile("mbarrier.arrive.expect_tx.shared.b64 _, [%0], %1;"
                 :: "r"(mbar), "r"(tx) : "memory");
}
__device__ __forceinline__ void mb_wait(uint32_t mbar, int parity) {
    asm volatile(
        "{\n\t.reg .pred P;\n"
        "WL%=:\n\t"
        "mbarrier.try_wait.parity.acquire.cta.shared::cta.b64 P, [%0], %1, 0x989680;\n\t"
        "@P bra WD%=;\n\t"
        "bra WL%=;\n"
        "WD%=:\n\t}"
        :: "r"(mbar), "r"(parity) : "memory");
}
// grid-wide barrier (monotonic counter, graph-replay safe)
__device__ __forceinline__ void gbar() {
    __syncthreads();
    if (threadIdx.x == 0) {
        __threadfence();
        unsigned long long arrive = atomicAdd(&g_bar_cnt, 1ULL);
        unsigned long long target = arrive / GRID_P + 1ULL;
        if ((arrive % GRID_P) == GRID_P - 1) {
            atomicAdd(&g_bar_gen, 1ULL);
        } else {
            unsigned long long g;
            do {
                __nanosleep(32);
                asm volatile("ld.acquire.gpu.global.u64 %0, [%1];"
                             : "=l"(g) : "l"(&g_bar_gen));
            } while (g < target);
        }
        __threadfence();
    }
    __syncthreads();
}

// ---------------- fused precompute kernel A: all weight conversions ----------
__global__ void k_prep_w(const float* __restrict__ Wih0, const float* __restrict__ Whh0,
                         const float* __restrict__ Wih1, const float* __restrict__ Whh1,
                         const float* __restrict__ Wl, const float* __restrict__ Wa,
                         const float* __restrict__ Wg, const float* __restrict__ x_enc) {
    const int stride = gridDim.x * blockDim.x;
    const int tid0 = blockIdx.x * blockDim.x + threadIdx.x;

    // W0q: [Wih0[:,512:] | Whh0], rows interleaved 4u+g, tile/quarter chunks + SWZ
    for (int i = tid0; i < 4096 * 256; i += stride) {
        int rn = i >> 8, c = (i & 255) * 8;
        int srow = (rn & 3) * 1024 + (rn >> 2);
        const float* s = (c < 1024) ? (Wih0 + (size_t)srow * 1536 + 512 + c)
                                    : (Whh0 + (size_t)srow * 1024 + (c - 1024));
        uint32_t off = SWZ((uint32_t)((rn & 31) * 1024 + (c & 511) * 2));
        char* d = (char*)g_W0q + (size_t)(rn >> 5) * 131072 + (size_t)(c >> 9) * 32768 + off;
        *(uint4*)d = pack8(((const float4*)s)[0], ((const float4*)s)[1]);
    }
    // W1q
    for (int i = tid0; i < 4096 * 256; i += stride) {
        int rn = i >> 8, c = (i & 255) * 8;
        int srow = (rn & 3) * 1024 + (rn >> 2);
        const float* s = (c < 1024) ? (Wih1 + (size_t)srow * 1024 + c)
                                    : (Whh1 + (size_t)srow * 1024 + (c - 1024));
        uint32_t off = SWZ((uint32_t)((rn & 31) * 1024 + (c & 511) * 2));
        char* d = (char*)g_W1q + (size_t)(rn >> 5) * 131072 + (size_t)(c >> 9) * 32768 + off;
        *(uint4*)d = pack8(((const float4*)s)[0], ((const float4*)s)[1]);
    }
    // Wlzq: Wl[:, :1024] -> 32 tiles x 2 quarters + SWZ
    for (int i = tid0; i < 1024 * 128; i += stride) {
        int rn = i >> 7, c = (i & 127) * 8;
        const float* s = Wl + (size_t)rn * 2048 + c;
        uint32_t off = SWZ((uint32_t)((rn & 31) * 1024 + (c & 511) * 2));
        char* d = (char*)g_Wlzq + (size_t)(rn >> 5) * 65536 + (size_t)(c >> 9) * 32768 + off;
        *(uint4*)d = pack8(((const float4*)s)[0], ((const float4*)s)[1]);
    }
    // W0e: Wih0[:,:512] interleaved rows, linear
    for (int i = tid0; i < 4096 * 64; i += stride) {
        int rn = i >> 6, c8 = (i & 63) * 8;
        int srow = (rn & 3) * 1024 + (rn >> 2);
        const float* s = Wih0 + (size_t)srow * 1536 + c8;
        ((uint4*)g_W0e)[i] = pack8(((const float4*)s)[0], ((const float4*)s)[1]);
    }
    // WaT: 1024x1024 transpose (scalar)
    for (int i = tid0; i < 1024 * 1024; i += stride) {
        int n = i >> 10, h = i & 1023;
        g_WaT[i] = __float2bfloat16(Wa[h * 1024 + n]);
    }
    // Wlc: Wl[:, 1024:]
    for (int i = tid0; i < 1024 * 128; i += stride) {
        int r = i >> 7, c8 = (i & 127) * 8;
        const float* s = Wl + (size_t)r * 2048 + 1024 + c8;
        ((uint4*)g_Wlc)[i] = pack8(((const float4*)s)[0], ((const float4*)s)[1]);
    }
    // Wg
    for (int i = tid0; i < 32000 * 128; i += stride) {
        const float4* s = (const float4*)Wg + (size_t)i * 2;
        ((uint4*)g_Wg)[i] = pack8(s[0], s[1]);
    }
    // xe
    for (int i = tid0; i < 2048 * 128; i += stride) {
        const float4* s = (const float4*)x_enc + (size_t)i * 2;
        ((uint4*)g_xe)[i] = pack8(s[0], s[1]);
    }
}

// ---------------- fused precompute kernel B: embed/init/biases/badot ---------
__global__ void k_prep_m(const int* __restrict__ x, const float* __restrict__ emb,
                         const float* __restrict__ h0in, const float* __restrict__ c0in,
                         const float* __restrict__ ba, const float* __restrict__ x_enc,
                         const float* __restrict__ bih0, const float* __restrict__ bhh0,
                         const float* __restrict__ bih1, const float* __restrict__ bhh1) {
    const int stride = gridDim.x * blockDim.x;
    const int tid0 = blockIdx.x * blockDim.x + threadIdx.x;

    // eseq embed (uint4 = 8 bf16)
    for (int i = tid0; i < NSTEP * NB * 64; i += stride) {
        int c8 = (i & 63) * 8;
        int m = i >> 6;
        int b = m & 31, t = m >> 5;
        int tok = x[b * TT + t];
        const float* s = emb + (size_t)tok * 512 + c8;
        ((uint4*)g_eseq)[i] = pack8(((const float4*)s)[0], ((const float4*)s)[1]);
    }
    // h/c init (chunked + SWZ h-layout)
    for (int i = tid0; i < NB * HH; i += stride) {
        int b = i >> 10, u = i & 1023;
        uint32_t off = (uint32_t)(u >> 9) * 32768 + SWZ((uint32_t)(b * 1024 + (u & 511) * 2));
        *(bf16*)((char*)g_h0buf + off) = __float2bfloat16(h0in[i]);
        *(bf16*)((char*)g_h1buf + off) = __float2bfloat16(h0in[NB * HH + i]);
        g_c0[i] = c0in[i];
        g_c1[i] = c0in[NB * HH + i];
    }
    // biases (interleaved 4u+g)
    for (int i = tid0; i < 4096; i += stride) {
        int u = i >> 2, g = i & 3;
        g_b0i[i] = bih0[g * 1024 + u] + bhh0[g * 1024 + u];
        g_b1i[i] = bih1[g * 1024 + u] + bhh1[g * 1024 + u];
    }
    // badot: one warp per row
    {
        int gw = tid0 >> 5, lane = threadIdx.x & 31;
        int nw = stride >> 5;
        for (int row = gw; row < 2048; row += nw) {
            const float* xr = x_enc + (size_t)row * 1024;
            float s = 0.f;
            for (int h = lane; h < 1024; h += 32) s += ba[h] * xr[h];
#pragma unroll
            for (int o = 16; o; o >>= 1) s += __shfl_xor_sync(0xffffffffu, s, o);
            if (lane == 0) g_badot[row] = s;
        }
    }
}

// ---------------- generic 128x128 GEMM (precompute) --------------------------
__global__ void __launch_bounds__(256) k_gemm_big(
    const bf16* __restrict__ A, const bf16* __restrict__ W,
    const float* __restrict__ bias, float* __restrict__ Cf, bf16* __restrict__ Cb,
    int N, int K, int mode)
{
    __shared__ __align__(16) bf16 As[128 * 40];
    __shared__ __align__(16) bf16 Bs[128 * 40];
    const int tid = threadIdx.x, warp = tid >> 5, lane = tid & 31;
    const int wr = warp >> 2, wc = warp & 3;
    const int mblk = blockIdx.y * 128;
    const int nblk = blockIdx.x * 128;
    const int sub = lane >> 3, ri = lane & 7;

    float acc[4][4][4];
#pragma unroll
    for (int a = 0; a < 4; a++)
#pragma unroll
        for (int b = 0; b < 4; b++)
#pragma unroll
            for (int c = 0; c < 4; c++) acc[a][b][c] = 0.f;

    for (int kb = 0; kb < K; kb += 32) {
        __syncthreads();
#pragma unroll
        for (int i = 0; i < 4; i++) {
            int v = tid + i * 256;
            if (v < 512) {
                int m = v >> 2, cv = v & 3;
                *(uint4*)&As[m * 40 + cv * 8] =
                    *(const uint4*)(A + (size_t)(mblk + m) * K + kb + cv * 8);
            } else {
                int u = v - 512;
                int n = u >> 2, cv = u & 3;
                *(uint4*)&Bs[n * 40 + cv * 8] =
                    *(const uint4*)(W + (size_t)(nblk + n) * K + kb + cv * 8);
            }
        }
        __syncthreads();
#pragma unroll
        for (int kk = 0; kk < 32; kk += 16) {
            uint32_t a[4][4], b[4][2];
#pragma unroll
            for (int mt = 0; mt < 4; mt++) {
                int row = wr * 64 + mt * 16 + (sub & 1) * 8 + ri;
                int col = kk + (sub >> 1) * 8;
                ldsm4(smem_u32(&As[row * 40 + col]), a[mt][0], a[mt][1], a[mt][2], a[mt][3]);
            }
#pragma unroll
            for (int ntp = 0; ntp < 2; ntp++) {
                int row = wc * 32 + ntp * 16 + (sub >> 1) * 8 + ri;
                int col = kk + (sub & 1) * 8;
                ldsm4(smem_u32(&Bs[row * 40 + col]),
                      b[ntp * 2][0], b[ntp * 2][1], b[ntp * 2 + 1][0], b[ntp * 2 + 1][1]);
            }
#pragma unroll
            for (int mt = 0; mt < 4; mt++)
#pragma unroll
                for (int nt = 0; nt < 4; nt++)
                    mma16816(acc[mt][nt], a[mt][0], a[mt][1], a[mt][2], a[mt][3],
                             b[nt][0], b[nt][1]);
        }
    }

    const int r0 = lane >> 2, c0 = (lane & 3) * 2;
#pragma unroll
    for (int mt = 0; mt < 4; mt++)
#pragma unroll
        for (int nt = 0; nt < 4; nt++) {
            int n = nblk + wc * 32 + nt * 8 + c0;
#pragma unroll
            for (int half = 0; half < 2; half++) {
                int m = mblk + wr * 64 + mt * 16 + r0 + half * 8;
                float v0 = acc[mt][nt][half * 2 + 0];
                float v1 = acc[mt][nt][half * 2 + 1];
                if (mode == 0) {
                    Cf[(size_t)m * N + n]     = v0 + bias[n];
                    Cf[(size_t)m * N + n + 1] = v1 + bias[n + 1];
                } else {
                    Cb[(size_t)m * N + n]     = __float2bfloat16(v0);
                    Cb[(size_t)m * N + n + 1] = __float2bfloat16(v1);
                }
            }
        }
}

// ---------------- persistent recurrence: TMA-fed step GEMM -------------------
// smem: A0 @0, W0 @32768, A1 @65536, W1 @98304, red @131072 (33792), mb @164864
#define SMOFF_A0  0
#define SMOFF_W0  32768
#define SMOFF_A1  65536
#define SMOFF_W1  98304
#define SMOFF_RED 131072
#define SMOFF_MB  164864
#define SMEM_RECUR 164896

__device__ __forceinline__ void comp_chunk(uint32_t aB, uint32_t wB,
                                           float acc[2][4][4]) {
    const int warp = threadIdx.x >> 5, lane = threadIdx.x & 31;
    const int sub = lane >> 3, ri = lane & 7;
#pragma unroll
    for (int kk = 0; kk < 64; kk += 16) {
        int col = (warp << 6) + kk;
        uint32_t a[2][4], b[4][2];
#pragma unroll
        for (int mt = 0; mt < 2; mt++) {
            uint32_t off = (uint32_t)((mt * 16 + (sub & 1) * 8 + ri) * 1024 +
                                      (col + (sub >> 1) * 8) * 2);
            ldsm4(aB + SWZ(off), a[mt][0], a[mt][1], a[mt][2], a[mt][3]);
        }
#pragma unroll
        for (int ntp = 0; ntp < 2; ntp++) {
            uint32_t off = (uint32_t)((ntp * 16 + (sub >> 1) * 8 + ri) * 1024 +
                                      (col + (sub & 1) * 8) * 2);
            ldsm4(wB + SWZ(off), b[ntp * 2][0], b[ntp * 2][1],
                  b[ntp * 2 + 1][0], b[ntp * 2 + 1][1]);
        }
#pragma unroll
        for (int mt = 0; mt < 2; mt++)
#pragma unroll
            for (int nt = 0; nt < 4; nt++)
                mma16816(acc[mt][nt], a[mt][0], a[mt][1], a[mt][2], a[mt][3],
                         b[nt][0], b[nt][1]);
    }
}

__device__ __forceinline__ void reduce32(char* sm, float acc[2][4][4], float out[4]) {
    float* red = (float*)(sm + SMOFF_RED);
    const int tid = threadIdx.x, warp = tid >> 5, lane = tid & 31;
    __syncthreads();
    float* rw = red + warp * (32 * 33);
#pragma unroll
    for (int mt = 0; mt < 2; mt++)
#pragma unroll
        for (int nt = 0; nt < 4; nt++) {
            int m = mt * 16 + (lane >> 2);
            int n0 = nt * 8 + (lane & 3) * 2;
            rw[m * 33 + n0]           = acc[mt][nt][0];
            rw[m * 33 + n0 + 1]       = acc[mt][nt][1];
            rw[(m + 8) * 33 + n0]     = acc[mt][nt][2];
            rw[(m + 8) * 33 + n0 + 1] = acc[mt][nt][3];
        }
    __syncthreads();
    int b = tid >> 3, ul = tid & 7;
#pragma unroll
    for (int g = 0; g < 4; g++) {
        float s = 0.f;
#pragma unroll
        for (int w = 0; w < 8; w++) s += red[w * (32 * 33) + b * 33 + ul * 4 + g];
        out[g] = s;
    }
}

// C[32,32] = A[32, nch*512] @ Wtile^T. Double-buffered TMA pipeline.
__device__ void gemm32t(const char* a0, const char* a1, const char* a2, const char* a3,
                        const char* wtile, int nch, char* sm, int2& ph, float out[4]) {
    const int tid = threadIdx.x;
    const char* ach[4] = {a0, a1, a2, a3};
    uint32_t smb = smem_u32(sm);
    uint32_t mb0 = smb + SMOFF_MB, mb1 = smb + SMOFF_MB + 8;
    float acc[2][4][4];
#pragma unroll
    for (int a = 0; a < 2; a++)
#pragma unroll
        for (int b = 0; b < 4; b++)
#pragma unroll
            for (int c = 0; c < 4; c++) acc[a][b][c] = 0.f;

    if (tid == 0) {
        mb_expect(mb0, 65536);
        tma1d(smb + SMOFF_A0, ach[0], 32768, mb0);
        tma1d(smb + SMOFF_W0, wtile, 32768, mb0);
    }
    for (int ch = 0; ch < nch; ch++) {
        int buf = ch & 1;
        if (ch + 1 < nch && tid == 0) {
            uint32_t mbn = buf ? mb0 : mb1;
            mb_expect(mbn, 65536);
            tma1d(smb + (buf ? SMOFF_A0 : SMOFF_A1), ach[ch + 1], 32768, mbn);
            tma1d(smb + (buf ? SMOFF_W0 : SMOFF_W1),
                  wtile + (size_t)(ch + 1) * 32768, 32768, mbn);
        }
        if (buf) { mb_wait(mb1, ph.y); ph.y ^= 1; }
        else     { mb_wait(mb0, ph.x); ph.x ^= 1; }
        comp_chunk(smb + (buf ? SMOFF_A1 : SMOFF_A0),
                   smb + (buf ? SMOFF_W1 : SMOFF_W0), acc);
        __syncthreads();
    }
    reduce32(sm, acc, out);
}

// ---------------- attention (device func) ------------------------------------
__device__ void attn_dev(int b, const char* __restrict__ h1base, char* smraw) {
    float* h1s = (float*)(smraw + SMOFF_RED);          // reuse red region
    float* sc = h1s + 1024;
    int tid = threadIdx.x;
    for (int u = tid; u < 1024; u += 256) {
        uint32_t off = (uint32_t)(u >> 9) * 32768 + SWZ((uint32_t)(b * 1024 + (u & 511) * 2));
        h1s[u] = __bfloat162float(*(const bf16*)(h1base + off));
    }
    __syncthreads();
    int warp = tid >> 5, lane = tid & 31;
#pragma unroll
    for (int jj = 0; jj < 8; jj++) {
        int j = warp * 8 + jj;
        const uint4* xr = (const uint4*)(g_xa + (size_t)(b * 64 + j) * 1024);
        float s = 0.f;
        for (int k4 = lane; k4 < 128; k4 += 32) {
            uint4 v = xr[k4];
            const __nv_bfloat162* p2 = (const __nv_bfloat162*)&v;
            int base = k4 * 8;
#pragma unroll
            for (int q = 0; q < 4; q++) {
                float2 f = __bfloat1622float2(p2[q]);
                s += h1s[base + q * 2] * f.x + h1s[base + q * 2 + 1] * f.y;
            }
        }
#pragma unroll
        for (int o = 16; o; o >>= 1) s += __shfl_xor_sync(0xffffffffu, s, o);
        if (lane == 0) sc[j] = s + g_badot[b * 64 + j];
    }
    __syncthreads();
    if (warp == 0) {
        float v0 = sc[lane], v1 = sc[lane + 32];
        float m = fmaxf(v0, v1);
#pragma unroll
        for (int o = 16; o; o >>= 1) m = fmaxf(m, __shfl_xor_sync(0xffffffffu, m, o));
        float e0 = expf(v0 - m), e1 = expf(v1 - m);
        float s = e0 + e1;
#pragma unroll
        for (int o = 16; o; o >>= 1) s += __shfl_xor_sync(0xffffffffu, s, o);
        sc[lane] = e0 / s;
        sc[lane + 32] = e1 / s;
    }
    __syncthreads();
    // ctx: 4 cols per thread, 8B loads
    {
        int n0 = tid * 4;
        float a0 = 0.f, a1 = 0.f, a2 = 0.f, a3 = 0.f;
        const char* base = (const char*)g_xc + (size_t)b * 131072 + n0 * 2;
#pragma unroll 8
        for (int j = 0; j < 64; j++) {
            uint2 v = *(const uint2*)(base + (size_t)j * 2048);
            float2 f0 = __bfloat1622float2(*(__nv_bfloat162*)&v.x);
            float2 f1 = __bfloat1622float2(*(__nv_bfloat162*)&v.y);
            float w = sc[j];
            a0 += w * f0.x; a1 += w * f0.y; a2 += w * f1.x; a3 += w * f1.y;
        }
        *(float4*)&g_ctxl[b * 1024 + n0] = make_float4(a0, a1, a2, a3);
    }
}

// ---------------- persistent recurrence kernel -------------------------------
__global__ void __launch_bounds__(256) k_recur(const float* __restrict__ bl) {
    extern __shared__ __align__(128) char smraw[];
    const int bid = blockIdx.x;
    const int tid = threadIdx.x;

    if (tid == 0) {
        mb_init(smem_u32(smraw) + SMOFF_MB);
        mb_init(smem_u32(smraw) + SMOFF_MB + 8);
    }
    asm volatile("fence.proxy.async.shared::cta;" ::: "memory");
    __syncthreads();
    int2 ph = make_int2(0, 0);

    for (int t = 0; t < NSTEP; t++) {
        const char* h0_in  = (const char*)g_h0buf + (t & 1) * 65536;
        char*       h0_out = (char*)g_h0buf + ((t + 1) & 1) * 65536;
        const char* h1_in  = (const char*)g_h1buf + (t & 1) * 65536;
        char*       h1_out = (char*)g_h1buf + ((t + 1) & 1) * 65536;
        const char* prev   = (const char*)g_outs + (size_t)t * 65536;

        // P1: layer-0 gates + cell (K=2048 = [prev | h0_in]; e-part from eg)
        if (bid < 128) {
            float s[4];
            gemm32t(prev, prev + 32768, h0_in, h0_in + 32768,
                    (const char*)g_W0q + (size_t)bid * 131072, 4, smraw, ph, s);
            const float* egp = g_eg + (size_t)t * 32 * 4096;
            int b = tid >> 3, ul = tid & 7;
            int rn = bid * 32 + ul * 4;
            int u = rn >> 2;
            float ig = s[0] + egp[b * 4096 + rn];
            float fg = s[1] + egp[b * 4096 + rn + 1];
            float gg = s[2] + egp[b * 4096 + rn + 2];
            float og = s[3] + egp[b * 4096 + rn + 3];
            float cn = sigmoidf_(fg) * g_c0[b * 1024 + u] + sigmoidf_(ig) * tanhf(gg);
            g_c0[b * 1024 + u] = cn;
            uint32_t off = (uint32_t)(u >> 9) * 32768 + SWZ((uint32_t)(b * 1024 + (u & 511) * 2));
            *(bf16*)(h0_out + off) = __float2bfloat16(sigmoidf_(og) * tanhf(cn));
        }
        gbar();

        // P2: layer-1 gates + cell (K=2048 = [h0_new | h1_prev])
        if (bid < 128) {
            float s[4];
            gemm32t(h0_out, h0_out + 32768, h1_in, h1_in + 32768,
                    (const char*)g_W1q + (size_t)bid * 131072, 4, smraw, ph, s);
            int b = tid >> 3, ul = tid & 7;
            int rn = bid * 32 + ul * 4;
            int u = rn >> 2;
            float ig = s[0] + g_b1i[rn];
            float fg = s[1] + g_b1i[rn + 1];
            float gg = s[2] + g_b1i[rn + 2];
            float og = s[3] + g_b1i[rn + 3];
            float cn = sigmoidf_(fg) * g_c1[b * 1024 + u] + sigmoidf_(ig) * tanhf(gg);
            g_c1[b * 1024 + u] = cn;
            uint32_t off = (uint32_t)(u >> 9) * 32768 + SWZ((uint32_t)(b * 1024 + (u & 511) * 2));
            *(bf16*)(h1_out + off) = __float2bfloat16(sigmoidf_(og) * tanhf(cn));
        }
        gbar();

        // P3: attention (blocks 0-31) || z @ Wlz^T (blocks 32-63)
        if (bid < 32) {
            attn_dev(bid, h1_out, smraw);
        } else if (bid < 64) {
            float s[4];
            gemm32t(h1_out, h1_out + 32768, h1_out, h1_out,
                    (const char*)g_Wlzq + (size_t)(bid - 32) * 65536, 2, smraw, ph, s);
            int b = tid >> 3, ul = tid & 7;
            int n = (bid - 32) * 32 + ul * 4;
#pragma unroll
            for (int g = 0; g < 4; g++) g_wl[b * 1024 + n + g] = s[g];
        }
        gbar();

        // P4: out = tanh(wl + bl + ctx) -> outs slot t+1 (chunked + SWZ)
        if (bid < 32) {
            char* outt = (char*)g_outs + (size_t)(t + 1) * 65536;
#pragma unroll
            for (int j = 0; j < 4; j++) {
                int n = tid * 4 + j;
                float v = g_wl[bid * 1024 + n] + bl[n] + g_ctxl[bid * 1024 + n];
                uint32_t off = (uint32_t)(n >> 9) * 32768 +
                               SWZ((uint32_t)(bid * 1024 + (n & 511) * 2));
                *(bf16*)(outt + off) = __float2bfloat16(tanhf(v));
            }
        }
        gbar();
    }
}

// ---------------- generator GEMM 256x128 tiles (A from chunked outs) ----------
__global__ void __launch_bounds__(256) k_gen(const bf16* __restrict__ W,
                                             const float* __restrict__ bias,
                                             float* __restrict__ out) {
    __shared__ __align__(16) bf16 As[256 * 40];
    __shared__ __align__(16) bf16 Ws[128 * 40];
    const int tid = threadIdx.x, warp = tid >> 5, lane = tid & 31;
    const int wr = warp >> 1, wc = warp & 1;
    const int mblk = blockIdx.y * 256;
    const int nblk = blockIdx.x * 128;
    const int sub = lane >> 3, ri = lane & 7;

    float acc[4][8][4];
#pragma unroll
    for (int a = 0; a < 4; a++)
#pragma unroll
        for (int b = 0; b < 8; b++)
#pragma unroll
            for (int c = 0; c < 4; c++) acc[a][b][c] = 0.f;

    for (int kb = 0; kb < 1024; kb += 32) {
        __syncthreads();
#pragma unroll
        for (int i = 0; i < 6; i++) {
            int v = tid + i * 256;
            if (v < 1024) {
                int m = v >> 2, cv = v & 3;
                int gm = mblk + m;
                int col = kb + cv * 8;
                size_t byteoff = (size_t)((gm >> 5) + 1) * 65536 +
                                 (size_t)(col >> 9) * 32768 +
                                 SWZ((uint32_t)((gm & 31) * 1024 + (col & 511) * 2));
                *(uint4*)&As[m * 40 + cv * 8] = *(const uint4*)((const char*)g_outs + byteoff);
            } else {
                int u = v - 1024;
                int n = u >> 2, cv = u & 3;
                *(uint4*)&Ws[n * 40 + cv * 8] =
                    *(const uint4*)(W + (size_t)(nblk + n) * 1024 + kb + cv * 8);
            }
        }
        __syncthreads();
#pragma unroll
        for (int kk = 0; kk < 32; kk += 16) {
            uint32_t a[4][4], b[8][2];
#pragma unroll
            for (int mt = 0; mt < 4; mt++) {
                int row = wr * 64 + mt * 16 + (sub & 1) * 8 + ri;
                int col = kk + (sub >> 1) * 8;
                ldsm4(smem_u32(&As[row * 40 + col]), a[mt][0], a[mt][1], a[mt][2], a[mt][3]);
            }
#pragma unroll
            for (int ntp = 0; ntp < 4; ntp++) {
                int row = wc * 64 + ntp * 16 + (sub >> 1) * 8 + ri;
                int col = kk + (sub & 1) * 8;
                ldsm4(smem_u32(&Ws[row * 40 + col]),
                      b[ntp * 2][0], b[ntp * 2][1], b[ntp * 2 + 1][0], b[ntp * 2 + 1][1]);
            }
#pragma unroll
            for (int mt = 0; mt < 4; mt++)
#pragma unroll
                for (int nt = 0; nt < 8; nt++)
                    mma16816(acc[mt][nt], a[mt][0], a[mt][1], a[mt][2], a[mt][3],
                             b[nt][0], b[nt][1]);
        }
    }

    const int r0 = lane >> 2, c0 = (lane & 3) * 2;
#pragma unroll
    for (int mt = 0; mt < 4; mt++)
#pragma unroll
        for (int nt = 0; nt < 8; nt++) {
            int n = nblk + wc * 64 + nt * 8 + c0;
            float bv0 = bias[n], bv1 = bias[n + 1];
#pragma unroll
            for (int half = 0; half < 2; half++) {
                int m = mblk + wr * 64 + mt * 16 + r0 + half * 8;
                if (m < NSTEP * NB) {
                    int t = m >> 5, bb = m & 31;
                    size_t orow = (size_t)(bb * NSTEP + t) * VV;
                    out[orow + n]     = acc[mt][nt][half * 2 + 0] + bv0;
                    out[orow + n + 1] = acc[mt][nt][half * 2 + 1] + bv1;
                }
            }
        }
}

// ---------------- log_softmax: online single-read -----------------------------
__global__ void __launch_bounds__(256) k_lsm(float* __restrict__ out) {
    int row = blockIdx.x;
    float4* p = (float4*)(out + (size_t)row * VV);
    __shared__ float sm_m[256];
    __shared__ float sm_s[256];
    int tid = threadIdx.x;
    float m = -1e30f, s = 0.f;
    for (int i = tid; i < 8000; i += 256) {
        float4 v = p[i];
        float x[4] = {v.x, v.y, v.z, v.w};
#pragma unroll
        for (int k = 0; k < 4; k++) {
            float nm = fmaxf(m, x[k]);
            s = s * __expf(m - nm) + __expf(x[k] - nm);
            m = nm;
        }
    }
    sm_m[tid] = m; sm_s[tid] = s;
    __syncthreads();
    for (int st = 128; st; st >>= 1) {
        if (tid < st) {
            float m2 = sm_m[tid + st], s2 = sm_s[tid + st];
            float nm = fmaxf(sm_m[tid], m2);
            sm_s[tid] = sm_s[tid] * __expf(sm_m[tid] - nm) + s2 * __expf(m2 - nm);
            sm_m[tid] = nm;
        }
        __syncthreads();
    }
    float lse = sm_m[0] + logf(sm_s[0]);
    for (int i = tid; i < 8000; i += 256) {
        float4 v = p[i];
        v.x -= lse; v.y -= lse; v.z -= lse; v.w -= lse;
        p[i] = v;
    }
}

// ---------------- host ---------------------------------------------------------
static void* sym(const void* s) {
    void* p = nullptr;
    cudaGetSymbolAddress(&p, s);
    return p;
}

extern "C" void kernel_launch(void* const* d_in, const int* in_sizes, int n_in,
                              void* d_out, int out_size) {
    const int*   x     = (const int*)d_in[0];
    const float* h0in  = (const float*)d_in[1];
    const float* c0in  = (const float*)d_in[2];
    const float* x_enc = (const float*)d_in[3];
    const float* emb   = (const float*)d_in[4];
    const float* Wih0  = (const float*)d_in[5];
    const float* Whh0  = (const float*)d_in[6];
    const float* bih0  = (const float*)d_in[7];
    const float* bhh0  = (const float*)d_in[8];
    const float* Wih1  = (const float*)d_in[9];
    const float* Whh1  = (const float*)d_in[10];
    const float* bih1  = (const float*)d_in[11];
    const float* bhh1  = (const float*)d_in[12];
    const float* Wa    = (const float*)d_in[13];
    const float* ba    = (const float*)d_in[14];
    const float* Wl    = (const float*)d_in[15];
    const float* bl    = (const float*)d_in[16];
    const float* Wg    = (const float*)d_in[17];
    const float* bg    = (const float*)d_in[18];
    float* out = (float*)d_out;

    bf16*  pW0e = (bf16*)sym(g_W0e);
    bf16*  pWaT = (bf16*)sym(g_WaT);
    bf16*  pWlc = (bf16*)sym(g_Wlc);
    bf16*  pWg  = (bf16*)sym(g_Wg);
    bf16*  pEs  = (bf16*)sym(g_eseq);
    float* pEg  = (float*)sym(g_eg);
    bf16*  pXe  = (bf16*)sym(g_xe);
    bf16*  pXa  = (bf16*)sym(g_xa);
    bf16*  pXc  = (bf16*)sym(g_xc);
    float* pB0i = (float*)sym(g_b0i);

    static bool attr_done = false;
    if (!attr_done) {
        cudaFuncSetAttribute(k_recur, cudaFuncAttributeMaxDynamicSharedMemorySize,
                             SMEM_RECUR);
        attr_done = true;
    }

    // ---- precompute: exactly 5 launches before k_recur ----
    k_prep_w<<<1024, 256>>>(Wih0, Whh0, Wih1, Whh1, Wl, Wa, Wg, x_enc);      // 1
    k_prep_m<<<256, 256>>>(x, emb, h0in, c0in, ba, x_enc,
                           bih0, bhh0, bih1, bhh1);                           // 2
    k_gemm_big<<<dim3(32, 16), 256>>>(pEs, pW0e, pB0i, pEg, nullptr,
                                      4096, 512, 0);                          // 3
    k_gemm_big<<<dim3(8, 16), 256>>>(pXe, pWaT, nullptr, nullptr, pXa,
                                     1024, 1024, 1);                          // 4
    k_gemm_big<<<dim3(8, 16), 256>>>(pXe, pWlc, nullptr, nullptr, pXc,
                                     1024, 1024, 1);                          // 5

    // ---- recurrence: ONE persistent kernel (launch #6 -> ncu capture) ----
    k_recur<<<GRID_P, 256, SMEM_RECUR>>>(bl);

    // ---- generator + log_softmax ----
    k_gen<<<dim3(250, 8), 256>>>(pWg, bg, out);
    k_lsm<<<NSTEP * NB, 256>>>(out);

    (void)in_sizes; (void)n_in; (void)out_size;
}

// round 10
// speedup vs baseline: 1.3200x; 1.0038x over previous
#include <cuda_runtime.h>
#include <cuda_bf16.h>
#include <cstdint>

typedef __nv_bfloat16 bf16;

#define NB 32
#define TT 64
#define NSTEP 63
#define HH 1024
#define VV 32000
#define GRID_P 128

// swizzle for 1024-byte-stride rows (32x512 bf16 chunks)
__device__ __forceinline__ uint32_t SWZ(uint32_t off) {
    return off ^ (((off >> 10) & 7u) << 4);
}

// ---------------- static scratch --------------------------------------------
__device__ __align__(128) bf16 g_W0q[4096 * 2048];  // 128 tiles x 4 q x 32KB, SWZ
__device__ __align__(128) bf16 g_W1q[4096 * 2048];
__device__ __align__(128) bf16 g_Wlzq[1024 * 1024]; // 32 tiles x 2 q x 32KB, SWZ
__device__ __align__(128) bf16 g_W0e[4096 * 512];   // interleaved rows, linear
__device__ __align__(128) bf16 g_WaT[1024 * 1024];
__device__ __align__(128) bf16 g_Wlc[1024 * 1024];
__device__ __align__(128) bf16 g_Wg [32000 * 1024];
__device__ __align__(128) bf16 g_eseq[2048 * 512];
__device__ __align__(128) float g_eg [2048 * 4096]; // e@W0e^T + b0 (interleaved cols)
__device__ __align__(128) bf16 g_xe[2048 * 1024];
__device__ __align__(128) bf16 g_xa[2048 * 1024];
__device__ __align__(128) bf16 g_xc[2048 * 1024];
// outs: 65 slots of 64KB; slot = 2 chunks x (32 b x 512 cols) swizzled; slot0 zeros
__device__ __align__(128) bf16 g_outs[2080 * 1024];
__device__ float g_b1i[4096];
__device__ float g_b0i[4096];
__device__ __align__(128) bf16 g_h0buf[2 * NB * HH]; // two 64KB chunked+SWZ bufs
__device__ __align__(128) bf16 g_h1buf[2 * NB * HH];
__device__ float g_c0[NB * HH];
__device__ float g_c1[NB * HH];
__device__ float g_ctxl[NB * HH];
__device__ float g_wl[NB * HH];
__device__ float g_badot[2048];
__device__ unsigned int g_flags[GRID_P];   // per-block arrival generations (monotonic)
__device__ unsigned int g_gen2;            // published generation (monotonic)

// ---------------- helpers ----------------------------------------------------
__device__ __forceinline__ uint32_t smem_u32(const void* p) {
    return (uint32_t)__cvta_generic_to_shared(p);
}
__device__ __forceinline__ void ldsm4(uint32_t addr, uint32_t& r0, uint32_t& r1,
                                      uint32_t& r2, uint32_t& r3) {
    asm volatile("ldmatrix.sync.aligned.m8n8.x4.shared.b16 {%0,%1,%2,%3}, [%4];"
                 : "=r"(r0), "=r"(r1), "=r"(r2), "=r"(r3) : "r"(addr));
}
__device__ __forceinline__ void mma16816(float* c, uint32_t a0, uint32_t a1,
                                         uint32_t a2, uint32_t a3,
                                         uint32_t b0, uint32_t b1) {
    asm volatile(
        "mma.sync.aligned.m16n8k16.row.col.f32.bf16.bf16.f32 "
        "{%0,%1,%2,%3},{%4,%5,%6,%7},{%8,%9},{%0,%1,%2,%3};"
        : "+f"(c[0]), "+f"(c[1]), "+f"(c[2]), "+f"(c[3])
        : "r"(a0), "r"(a1), "r"(a2), "r"(a3), "r"(b0), "r"(b1));
}
__device__ __forceinline__ float sigmoidf_(float x) { return 1.f / (1.f + expf(-x)); }
__device__ __forceinline__ uint4 pack8(float4 a, float4 b) {
    uint4 o;
    __nv_bfloat162 p;
    p = __floats2bfloat162_rn(a.x, a.y); o.x = *(uint32_t*)&p;
    p = __floats2bfloat162_rn(a.z, a.w); o.y = *(uint32_t*)&p;
    p = __floats2bfloat162_rn(b.x, b.y); o.z = *(uint32_t*)&p;
    p = __floats2bfloat162_rn(b.z, b.w); o.w = *(uint32_t*)&p;
    return o;
}
// --- 1D TMA bulk + mbarrier ---
__device__ __forceinline__ void tma1d(uint32_t dst, const void* src, uint32_t bytes,
                                      uint32_t mbar) {
    asm volatile(
        "cp.async.bulk.shared::cluster.global.mbarrier::complete_tx::bytes "
        "[%0], [%1], %2, [%3];"
        :: "r"(dst), "l"(src), "r"(bytes), "r"(mbar) : "memory");
}
__device__ __forceinline__ void mb_init(uint32_t mbar) {
    asm volatile("mbarrier.init.shared.b64 [%0], 1;" :: "r"(mbar) : "memory");
}
__device__ __forceinline__ void mb_expect(uint32_t mbar, uint32_t tx) {
    asm volatile("mbarrier.arrive.expect_tx.shared.b64 _, [%0], %1;"
                 :: "r"(mbar), "r"(tx) : "memory");
}
__device__ __forceinline__ void mb_wait(uint32_t mbar, int parity) {
    asm volatile(
        "{\n\t.reg .pred P;\n"
        "WL%=:\n\t"
        "mbarrier.try_wait.parity.acquire.cta.shared::cta.b64 P, [%0], %1, 0x989680;\n\t"
        "@P bra WD%=;\n\t"
        "bra WL%=;\n"
        "WD%=:\n\t}"
        :: "r"(mbar), "r"(parity) : "memory");
}
// ---- contention-free grid barrier: per-block flags + published generation ----
__device__ __forceinline__ void gbar(unsigned int& gen) {
    gen++;
    __syncthreads();
    const int tid = threadIdx.x;
    const int bid = blockIdx.x;
    if (bid == 0) {
        if (tid == 0) {
            __threadfence();
            asm volatile("st.release.gpu.global.u32 [%0], %1;"
                         :: "l"(&g_flags[0]), "r"(gen) : "memory");
        }
        if (tid < GRID_P) {
            unsigned int v;
            do {
                __nanosleep(20);
                asm volatile("ld.acquire.gpu.global.u32 %0, [%1];"
                             : "=r"(v) : "l"(&g_flags[tid]));
            } while (v < gen);
        }
        __syncthreads();
        if (tid == 0) {
            asm volatile("st.release.gpu.global.u32 [%0], %1;"
                         :: "l"(&g_gen2), "r"(gen) : "memory");
        }
    } else {
        if (tid == 0) {
            __threadfence();
            asm volatile("st.release.gpu.global.u32 [%0], %1;"
                         :: "l"(&g_flags[bid]), "r"(gen) : "memory");
            unsigned int v;
            do {
                __nanosleep(20);
                asm volatile("ld.acquire.gpu.global.u32 %0, [%1];"
                             : "=r"(v) : "l"(&g_gen2));
            } while (v < gen);
        }
        __syncthreads();
    }
}

// ---------------- fused precompute kernel A: all weight conversions ----------
__global__ void k_prep_w(const float* __restrict__ Wih0, const float* __restrict__ Whh0,
                         const float* __restrict__ Wih1, const float* __restrict__ Whh1,
                         const float* __restrict__ Wl, const float* __restrict__ Wa,
                         const float* __restrict__ Wg, const float* __restrict__ x_enc) {
    const int stride = gridDim.x * blockDim.x;
    const int tid0 = blockIdx.x * blockDim.x + threadIdx.x;

    // W0q: [Wih0[:,512:] | Whh0], rows interleaved 4u+g, tile/quarter chunks + SWZ
    for (int i = tid0; i < 4096 * 256; i += stride) {
        int rn = i >> 8, c = (i & 255) * 8;
        int srow = (rn & 3) * 1024 + (rn >> 2);
        const float* s = (c < 1024) ? (Wih0 + (size_t)srow * 1536 + 512 + c)
                                    : (Whh0 + (size_t)srow * 1024 + (c - 1024));
        uint32_t off = SWZ((uint32_t)((rn & 31) * 1024 + (c & 511) * 2));
        char* d = (char*)g_W0q + (size_t)(rn >> 5) * 131072 + (size_t)(c >> 9) * 32768 + off;
        *(uint4*)d = pack8(((const float4*)s)[0], ((const float4*)s)[1]);
    }
    // W1q
    for (int i = tid0; i < 4096 * 256; i += stride) {
        int rn = i >> 8, c = (i & 255) * 8;
        int srow = (rn & 3) * 1024 + (rn >> 2);
        const float* s = (c < 1024) ? (Wih1 + (size_t)srow * 1024 + c)
                                    : (Whh1 + (size_t)srow * 1024 + (c - 1024));
        uint32_t off = SWZ((uint32_t)((rn & 31) * 1024 + (c & 511) * 2));
        char* d = (char*)g_W1q + (size_t)(rn >> 5) * 131072 + (size_t)(c >> 9) * 32768 + off;
        *(uint4*)d = pack8(((const float4*)s)[0], ((const float4*)s)[1]);
    }
    // Wlzq: Wl[:, :1024] -> 32 tiles x 2 quarters + SWZ
    for (int i = tid0; i < 1024 * 128; i += stride) {
        int rn = i >> 7, c = (i & 127) * 8;
        const float* s = Wl + (size_t)rn * 2048 + c;
        uint32_t off = SWZ((uint32_t)((rn & 31) * 1024 + (c & 511) * 2));
        char* d = (char*)g_Wlzq + (size_t)(rn >> 5) * 65536 + (size_t)(c >> 9) * 32768 + off;
        *(uint4*)d = pack8(((const float4*)s)[0], ((const float4*)s)[1]);
    }
    // W0e: Wih0[:,:512] interleaved rows, linear
    for (int i = tid0; i < 4096 * 64; i += stride) {
        int rn = i >> 6, c8 = (i & 63) * 8;
        int srow = (rn & 3) * 1024 + (rn >> 2);
        const float* s = Wih0 + (size_t)srow * 1536 + c8;
        ((uint4*)g_W0e)[i] = pack8(((const float4*)s)[0], ((const float4*)s)[1]);
    }
    // WaT: 1024x1024 transpose (scalar)
    for (int i = tid0; i < 1024 * 1024; i += stride) {
        int n = i >> 10, h = i & 1023;
        g_WaT[i] = __float2bfloat16(Wa[h * 1024 + n]);
    }
    // Wlc: Wl[:, 1024:]
    for (int i = tid0; i < 1024 * 128; i += stride) {
        int r = i >> 7, c8 = (i & 127) * 8;
        const float* s = Wl + (size_t)r * 2048 + 1024 + c8;
        ((uint4*)g_Wlc)[i] = pack8(((const float4*)s)[0], ((const float4*)s)[1]);
    }
    // Wg
    for (int i = tid0; i < 32000 * 128; i += stride) {
        const float4* s = (const float4*)Wg + (size_t)i * 2;
        ((uint4*)g_Wg)[i] = pack8(s[0], s[1]);
    }
    // xe
    for (int i = tid0; i < 2048 * 128; i += stride) {
        const float4* s = (const float4*)x_enc + (size_t)i * 2;
        ((uint4*)g_xe)[i] = pack8(s[0], s[1]);
    }
}

// ---------------- fused precompute kernel B: embed/init/biases/badot ---------
__global__ void k_prep_m(const int* __restrict__ x, const float* __restrict__ emb,
                         const float* __restrict__ h0in, const float* __restrict__ c0in,
                         const float* __restrict__ ba, const float* __restrict__ x_enc,
                         const float* __restrict__ bih0, const float* __restrict__ bhh0,
                         const float* __restrict__ bih1, const float* __restrict__ bhh1) {
    const int stride = gridDim.x * blockDim.x;
    const int tid0 = blockIdx.x * blockDim.x + threadIdx.x;

    for (int i = tid0; i < NSTEP * NB * 64; i += stride) {
        int c8 = (i & 63) * 8;
        int m = i >> 6;
        int b = m & 31, t = m >> 5;
        int tok = x[b * TT + t];
        const float* s = emb + (size_t)tok * 512 + c8;
        ((uint4*)g_eseq)[i] = pack8(((const float4*)s)[0], ((const float4*)s)[1]);
    }
    for (int i = tid0; i < NB * HH; i += stride) {
        int b = i >> 10, u = i & 1023;
        uint32_t off = (uint32_t)(u >> 9) * 32768 + SWZ((uint32_t)(b * 1024 + (u & 511) * 2));
        *(bf16*)((char*)g_h0buf + off) = __float2bfloat16(h0in[i]);
        *(bf16*)((char*)g_h1buf + off) = __float2bfloat16(h0in[NB * HH + i]);
        g_c0[i] = c0in[i];
        g_c1[i] = c0in[NB * HH + i];
    }
    for (int i = tid0; i < 4096; i += stride) {
        int u = i >> 2, g = i & 3;
        g_b0i[i] = bih0[g * 1024 + u] + bhh0[g * 1024 + u];
        g_b1i[i] = bih1[g * 1024 + u] + bhh1[g * 1024 + u];
    }
    {
        int gw = tid0 >> 5, lane = threadIdx.x & 31;
        int nw = stride >> 5;
        for (int row = gw; row < 2048; row += nw) {
            const float* xr = x_enc + (size_t)row * 1024;
            float s = 0.f;
            for (int h = lane; h < 1024; h += 32) s += ba[h] * xr[h];
#pragma unroll
            for (int o = 16; o; o >>= 1) s += __shfl_xor_sync(0xffffffffu, s, o);
            if (lane == 0) g_badot[row] = s;
        }
    }
}

// ---------------- generic 128x128 GEMM (eg precompute) -----------------------
__global__ void __launch_bounds__(256) k_gemm_big(
    const bf16* __restrict__ A, const bf16* __restrict__ W,
    const float* __restrict__ bias, float* __restrict__ Cf,
    int N, int K)
{
    __shared__ __align__(16) bf16 As[128 * 40];
    __shared__ __align__(16) bf16 Bs[128 * 40];
    const int tid = threadIdx.x, warp = tid >> 5, lane = tid & 31;
    const int wr = warp >> 2, wc = warp & 3;
    const int mblk = blockIdx.y * 128;
    const int nblk = blockIdx.x * 128;
    const int sub = lane >> 3, ri = lane & 7;

    float acc[4][4][4];
#pragma unroll
    for (int a = 0; a < 4; a++)
#pragma unroll
        for (int b = 0; b < 4; b++)
#pragma unroll
            for (int c = 0; c < 4; c++) acc[a][b][c] = 0.f;

    for (int kb = 0; kb < K; kb += 32) {
        __syncthreads();
#pragma unroll
        for (int i = 0; i < 4; i++) {
            int v = tid + i * 256;
            if (v < 512) {
                int m = v >> 2, cv = v & 3;
                *(uint4*)&As[m * 40 + cv * 8] =
                    *(const uint4*)(A + (size_t)(mblk + m) * K + kb + cv * 8);
            } else {
                int u = v - 512;
                int n = u >> 2, cv = u & 3;
                *(uint4*)&Bs[n * 40 + cv * 8] =
                    *(const uint4*)(W + (size_t)(nblk + n) * K + kb + cv * 8);
            }
        }
        __syncthreads();
#pragma unroll
        for (int kk = 0; kk < 32; kk += 16) {
            uint32_t a[4][4], b[4][2];
#pragma unroll
            for (int mt = 0; mt < 4; mt++) {
                int row = wr * 64 + mt * 16 + (sub & 1) * 8 + ri;
                int col = kk + (sub >> 1) * 8;
                ldsm4(smem_u32(&As[row * 40 + col]), a[mt][0], a[mt][1], a[mt][2], a[mt][3]);
            }
#pragma unroll
            for (int ntp = 0; ntp < 2; ntp++) {
                int row = wc * 32 + ntp * 16 + (sub >> 1) * 8 + ri;
                int col = kk + (sub & 1) * 8;
                ldsm4(smem_u32(&Bs[row * 40 + col]),
                      b[ntp * 2][0], b[ntp * 2][1], b[ntp * 2 + 1][0], b[ntp * 2 + 1][1]);
            }
#pragma unroll
            for (int mt = 0; mt < 4; mt++)
#pragma unroll
                for (int nt = 0; nt < 4; nt++)
                    mma16816(acc[mt][nt], a[mt][0], a[mt][1], a[mt][2], a[mt][3],
                             b[nt][0], b[nt][1]);
        }
    }

    const int r0 = lane >> 2, c0 = (lane & 3) * 2;
#pragma unroll
    for (int mt = 0; mt < 4; mt++)
#pragma unroll
        for (int nt = 0; nt < 4; nt++) {
            int n = nblk + wc * 32 + nt * 8 + c0;
#pragma unroll
            for (int half = 0; half < 2; half++) {
                int m = mblk + wr * 64 + mt * 16 + r0 + half * 8;
                Cf[(size_t)m * N + n]     = acc[mt][nt][half * 2 + 0] + bias[n];
                Cf[(size_t)m * N + n + 1] = acc[mt][nt][half * 2 + 1] + bias[n + 1];
            }
        }
}

// ---------------- fused xa/xc GEMM (z=0: xe@WaT->xa, z=1: xe@Wlc->xc) --------
__global__ void __launch_bounds__(256) k_gemm_x2() {
    const bf16* A = g_xe;
    const bf16* W = (blockIdx.z == 0) ? g_WaT : g_Wlc;
    bf16* Cb      = (blockIdx.z == 0) ? g_xa : g_xc;
    const int K = 1024, N = 1024;

    __shared__ __align__(16) bf16 As[128 * 40];
    __shared__ __align__(16) bf16 Bs[128 * 40];
    const int tid = threadIdx.x, warp = tid >> 5, lane = tid & 31;
    const int wr = warp >> 2, wc = warp & 3;
    const int mblk = blockIdx.y * 128;
    const int nblk = blockIdx.x * 128;
    const int sub = lane >> 3, ri = lane & 7;

    float acc[4][4][4];
#pragma unroll
    for (int a = 0; a < 4; a++)
#pragma unroll
        for (int b = 0; b < 4; b++)
#pragma unroll
            for (int c = 0; c < 4; c++) acc[a][b][c] = 0.f;

    for (int kb = 0; kb < K; kb += 32) {
        __syncthreads();
#pragma unroll
        for (int i = 0; i < 4; i++) {
            int v = tid + i * 256;
            if (v < 512) {
                int m = v >> 2, cv = v & 3;
                *(uint4*)&As[m * 40 + cv * 8] =
                    *(const uint4*)(A + (size_t)(mblk + m) * K + kb + cv * 8);
            } else {
                int u = v - 512;
                int n = u >> 2, cv = u & 3;
                *(uint4*)&Bs[n * 40 + cv * 8] =
                    *(const uint4*)(W + (size_t)(nblk + n) * K + kb + cv * 8);
            }
        }
        __syncthreads();
#pragma unroll
        for (int kk = 0; kk < 32; kk += 16) {
            uint32_t a[4][4], b[4][2];
#pragma unroll
            for (int mt = 0; mt < 4; mt++) {
                int row = wr * 64 + mt * 16 + (sub & 1) * 8 + ri;
                int col = kk + (sub >> 1) * 8;
                ldsm4(smem_u32(&As[row * 40 + col]), a[mt][0], a[mt][1], a[mt][2], a[mt][3]);
            }
#pragma unroll
            for (int ntp = 0; ntp < 2; ntp++) {
                int row = wc * 32 + ntp * 16 + (sub >> 1) * 8 + ri;
                int col = kk + (sub & 1) * 8;
                ldsm4(smem_u32(&Bs[row * 40 + col]),
                      b[ntp * 2][0], b[ntp * 2][1], b[ntp * 2 + 1][0], b[ntp * 2 + 1][1]);
            }
#pragma unroll
            for (int mt = 0; mt < 4; mt++)
#pragma unroll
                for (int nt = 0; nt < 4; nt++)
                    mma16816(acc[mt][nt], a[mt][0], a[mt][1], a[mt][2], a[mt][3],
                             b[nt][0], b[nt][1]);
        }
    }

    const int r0 = lane >> 2, c0 = (lane & 3) * 2;
#pragma unroll
    for (int mt = 0; mt < 4; mt++)
#pragma unroll
        for (int nt = 0; nt < 4; nt++) {
            int n = nblk + wc * 32 + nt * 8 + c0;
#pragma unroll
            for (int half = 0; half < 2; half++) {
                int m = mblk + wr * 64 + mt * 16 + r0 + half * 8;
                Cb[(size_t)m * N + n]     = __float2bfloat16(acc[mt][nt][half * 2 + 0]);
                Cb[(size_t)m * N + n + 1] = __float2bfloat16(acc[mt][nt][half * 2 + 1]);
            }
        }
}

// ---------------- persistent recurrence: TMA-fed step GEMM -------------------
// smem: A0 @0, W0 @32768, A1 @65536, W1 @98304, red @131072 (33792), mb @164864
#define SMOFF_A0  0
#define SMOFF_W0  32768
#define SMOFF_A1  65536
#define SMOFF_W1  98304
#define SMOFF_RED 131072
#define SMOFF_MB  164864
#define SMEM_RECUR 164896

__device__ __forceinline__ void comp_chunk(uint32_t aB, uint32_t wB,
                                           float acc[2][4][4]) {
    const int warp = threadIdx.x >> 5, lane = threadIdx.x & 31;
    const int sub = lane >> 3, ri = lane & 7;
#pragma unroll
    for (int kk = 0; kk < 64; kk += 16) {
        int col = (warp << 6) + kk;
        uint32_t a[2][4], b[4][2];
#pragma unroll
        for (int mt = 0; mt < 2; mt++) {
            uint32_t off = (uint32_t)((mt * 16 + (sub & 1) * 8 + ri) * 1024 +
                                      (col + (sub >> 1) * 8) * 2);
            ldsm4(aB + SWZ(off), a[mt][0], a[mt][1], a[mt][2], a[mt][3]);
        }
#pragma unroll
        for (int ntp = 0; ntp < 2; ntp++) {
            uint32_t off = (uint32_t)((ntp * 16 + (sub >> 1) * 8 + ri) * 1024 +
                                      (col + (sub & 1) * 8) * 2);
            ldsm4(wB + SWZ(off), b[ntp * 2][0], b[ntp * 2][1],
                  b[ntp * 2 + 1][0], b[ntp * 2 + 1][1]);
        }
#pragma unroll
        for (int mt = 0; mt < 2; mt++)
#pragma unroll
            for (int nt = 0; nt < 4; nt++)
                mma16816(acc[mt][nt], a[mt][0], a[mt][1], a[mt][2], a[mt][3],
                         b[nt][0], b[nt][1]);
    }
}

__device__ __forceinline__ void reduce32(char* sm, float acc[2][4][4], float out[4]) {
    float* red = (float*)(sm + SMOFF_RED);
    const int tid = threadIdx.x, warp = tid >> 5, lane = tid & 31;
    __syncthreads();
    float* rw = red + warp * (32 * 33);
#pragma unroll
    for (int mt = 0; mt < 2; mt++)
#pragma unroll
        for (int nt = 0; nt < 4; nt++) {
            int m = mt * 16 + (lane >> 2);
            int n0 = nt * 8 + (lane & 3) * 2;
            rw[m * 33 + n0]           = acc[mt][nt][0];
            rw[m * 33 + n0 + 1]       = acc[mt][nt][1];
            rw[(m + 8) * 33 + n0]     = acc[mt][nt][2];
            rw[(m + 8) * 33 + n0 + 1] = acc[mt][nt][3];
        }
    __syncthreads();
    int b = tid >> 3, ul = tid & 7;
#pragma unroll
    for (int g = 0; g < 4; g++) {
        float s = 0.f;
#pragma unroll
        for (int w = 0; w < 8; w++) s += red[w * (32 * 33) + b * 33 + ul * 4 + g];
        out[g] = s;
    }
}

// C[32,32] = A[32, nch*512] @ Wtile^T. Double-buffered TMA pipeline.
__device__ void gemm32t(const char* a0, const char* a1, const char* a2, const char* a3,
                        const char* wtile, int nch, char* sm, int2& ph, float out[4]) {
    const int tid = threadIdx.x;
    const char* ach[4] = {a0, a1, a2, a3};
    uint32_t smb = smem_u32(sm);
    uint32_t mb0 = smb + SMOFF_MB, mb1 = smb + SMOFF_MB + 8;
    float acc[2][4][4];
#pragma unroll
    for (int a = 0; a < 2; a++)
#pragma unroll
        for (int b = 0; b < 4; b++)
#pragma unroll
            for (int c = 0; c < 4; c++) acc[a][b][c] = 0.f;

    if (tid == 0) {
        mb_expect(mb0, 65536);
        tma1d(smb + SMOFF_A0, ach[0], 32768, mb0);
        tma1d(smb + SMOFF_W0, wtile, 32768, mb0);
    }
    for (int ch = 0; ch < nch; ch++) {
        int buf = ch & 1;
        if (ch + 1 < nch && tid == 0) {
            uint32_t mbn = buf ? mb0 : mb1;
            mb_expect(mbn, 65536);
            tma1d(smb + (buf ? SMOFF_A0 : SMOFF_A1), ach[ch + 1], 32768, mbn);
            tma1d(smb + (buf ? SMOFF_W0 : SMOFF_W1),
                  wtile + (size_t)(ch + 1) * 32768, 32768, mbn);
        }
        if (buf) { mb_wait(mb1, ph.y); ph.y ^= 1; }
        else     { mb_wait(mb0, ph.x); ph.x ^= 1; }
        comp_chunk(smb + (buf ? SMOFF_A1 : SMOFF_A0),
                   smb + (buf ? SMOFF_W1 : SMOFF_W0), acc);
        __syncthreads();
    }
    reduce32(sm, acc, out);
}

// ---------------- attention (device func) ------------------------------------
__device__ void attn_dev(int b, const char* __restrict__ h1base, char* smraw) {
    float* h1s = (float*)(smraw + SMOFF_RED);
    float* sc = h1s + 1024;
    int tid = threadIdx.x;
    for (int u = tid; u < 1024; u += 256) {
        uint32_t off = (uint32_t)(u >> 9) * 32768 + SWZ((uint32_t)(b * 1024 + (u & 511) * 2));
        h1s[u] = __bfloat162float(*(const bf16*)(h1base + off));
    }
    __syncthreads();
    int warp = tid >> 5, lane = tid & 31;
#pragma unroll
    for (int jj = 0; jj < 8; jj++) {
        int j = warp * 8 + jj;
        const uint4* xr = (const uint4*)(g_xa + (size_t)(b * 64 + j) * 1024);
        float s = 0.f;
        for (int k4 = lane; k4 < 128; k4 += 32) {
            uint4 v = xr[k4];
            const __nv_bfloat162* p2 = (const __nv_bfloat162*)&v;
            int base = k4 * 8;
#pragma unroll
            for (int q = 0; q < 4; q++) {
                float2 f = __bfloat1622float2(p2[q]);
                s += h1s[base + q * 2] * f.x + h1s[base + q * 2 + 1] * f.y;
            }
        }
#pragma unroll
        for (int o = 16; o; o >>= 1) s += __shfl_xor_sync(0xffffffffu, s, o);
        if (lane == 0) sc[j] = s + g_badot[b * 64 + j];
    }
    __syncthreads();
    if (warp == 0) {
        float v0 = sc[lane], v1 = sc[lane + 32];
        float m = fmaxf(v0, v1);
#pragma unroll
        for (int o = 16; o; o >>= 1) m = fmaxf(m, __shfl_xor_sync(0xffffffffu, m, o));
        float e0 = expf(v0 - m), e1 = expf(v1 - m);
        float s = e0 + e1;
#pragma unroll
        for (int o = 16; o; o >>= 1) s += __shfl_xor_sync(0xffffffffu, s, o);
        sc[lane] = e0 / s;
        sc[lane + 32] = e1 / s;
    }
    __syncthreads();
    {
        int n0 = tid * 4;
        float a0 = 0.f, a1 = 0.f, a2 = 0.f, a3 = 0.f;
        const char* base = (const char*)g_xc + (size_t)b * 131072 + n0 * 2;
#pragma unroll 8
        for (int j = 0; j < 64; j++) {
            uint2 v = *(const uint2*)(base + (size_t)j * 2048);
            float2 f0 = __bfloat1622float2(*(__nv_bfloat162*)&v.x);
            float2 f1 = __bfloat1622float2(*(__nv_bfloat162*)&v.y);
            float w = sc[j];
            a0 += w * f0.x; a1 += w * f0.y; a2 += w * f1.x; a3 += w * f1.y;
        }
        *(float4*)&g_ctxl[b * 1024 + n0] = make_float4(a0, a1, a2, a3);
    }
}

// ---------------- persistent recurrence kernel -------------------------------
__global__ void __launch_bounds__(256) k_recur(const float* __restrict__ bl) {
    extern __shared__ __align__(128) char smraw[];
    const int bid = blockIdx.x;
    const int tid = threadIdx.x;

    if (tid == 0) {
        mb_init(smem_u32(smraw) + SMOFF_MB);
        mb_init(smem_u32(smraw) + SMOFF_MB + 8);
    }
    asm volatile("fence.proxy.async.shared::cta;" ::: "memory");
    __syncthreads();
    int2 ph = make_int2(0, 0);
    unsigned int gen;
    asm volatile("ld.acquire.gpu.global.u32 %0, [%1];" : "=r"(gen) : "l"(&g_gen2));

    for (int t = 0; t < NSTEP; t++) {
        const char* h0_in  = (const char*)g_h0buf + (t & 1) * 65536;
        char*       h0_out = (char*)g_h0buf + ((t + 1) & 1) * 65536;
        const char* h1_in  = (const char*)g_h1buf + (t & 1) * 65536;
        char*       h1_out = (char*)g_h1buf + ((t + 1) & 1) * 65536;
        const char* prev   = (const char*)g_outs + (size_t)t * 65536;

        // P1: layer-0 gates + cell (K=2048 = [prev | h0_in]; e-part from eg)
        {
            float s[4];
            gemm32t(prev, prev + 32768, h0_in, h0_in + 32768,
                    (const char*)g_W0q + (size_t)bid * 131072, 4, smraw, ph, s);
            const float* egp = g_eg + (size_t)t * 32 * 4096;
            int b = tid >> 3, ul = tid & 7;
            int rn = bid * 32 + ul * 4;
            int u = rn >> 2;
            float ig = s[0] + egp[b * 4096 + rn];
            float fg = s[1] + egp[b * 4096 + rn + 1];
            float gg = s[2] + egp[b * 4096 + rn + 2];
            float og = s[3] + egp[b * 4096 + rn + 3];
            float cn = sigmoidf_(fg) * g_c0[b * 1024 + u] + sigmoidf_(ig) * tanhf(gg);
            g_c0[b * 1024 + u] = cn;
            uint32_t off = (uint32_t)(u >> 9) * 32768 + SWZ((uint32_t)(b * 1024 + (u & 511) * 2));
            *(bf16*)(h0_out + off) = __float2bfloat16(sigmoidf_(og) * tanhf(cn));
        }
        gbar(gen);

        // P2: layer-1 gates + cell (K=2048 = [h0_new | h1_prev])
        {
            float s[4];
            gemm32t(h0_out, h0_out + 32768, h1_in, h1_in + 32768,
                    (const char*)g_W1q + (size_t)bid * 131072, 4, smraw, ph, s);
            int b = tid >> 3, ul = tid & 7;
            int rn = bid * 32 + ul * 4;
            int u = rn >> 2;
            float ig = s[0] + g_b1i[rn];
            float fg = s[1] + g_b1i[rn + 1];
            float gg = s[2] + g_b1i[rn + 2];
            float og = s[3] + g_b1i[rn + 3];
            float cn = sigmoidf_(fg) * g_c1[b * 1024 + u] + sigmoidf_(ig) * tanhf(gg);
            g_c1[b * 1024 + u] = cn;
            uint32_t off = (uint32_t)(u >> 9) * 32768 + SWZ((uint32_t)(b * 1024 + (u & 511) * 2));
            *(bf16*)(h1_out + off) = __float2bfloat16(sigmoidf_(og) * tanhf(cn));
        }
        gbar(gen);

        // P3: attention (blocks 0-31) || z @ Wlz^T (blocks 32-63)
        if (bid < 32) {
            attn_dev(bid, h1_out, smraw);
        } else if (bid < 64) {
            float s[4];
            gemm32t(h1_out, h1_out + 32768, h1_out, h1_out,
                    (const char*)g_Wlzq + (size_t)(bid - 32) * 65536, 2, smraw, ph, s);
            int b = tid >> 3, ul = tid & 7;
            int n = (bid - 32) * 32 + ul * 4;
#pragma unroll
            for (int g = 0; g < 4; g++) g_wl[b * 1024 + n + g] = s[g];
        }
        gbar(gen);

        // P4: out = tanh(wl + bl + ctx) -> outs slot t+1 (chunked + SWZ)
        if (bid < 32) {
            char* outt = (char*)g_outs + (size_t)(t + 1) * 65536;
#pragma unroll
            for (int j = 0; j < 4; j++) {
                int n = tid * 4 + j;
                float v = g_wl[bid * 1024 + n] + bl[n] + g_ctxl[bid * 1024 + n];
                uint32_t off = (uint32_t)(n >> 9) * 32768 +
                               SWZ((uint32_t)(bid * 1024 + (n & 511) * 2));
                *(bf16*)(outt + off) = __float2bfloat16(tanhf(v));
            }
        }
        gbar(gen);
    }
}

// ---------------- generator GEMM 256x128 tiles (A from chunked outs) ----------
__global__ void __launch_bounds__(256) k_gen(const bf16* __restrict__ W,
                                             const float* __restrict__ bias,
                                             float* __restrict__ out) {
    __shared__ __align__(16) bf16 As[256 * 40];
    __shared__ __align__(16) bf16 Ws[128 * 40];
    const int tid = threadIdx.x, warp = tid >> 5, lane = tid & 31;
    const int wr = warp >> 1, wc = warp & 1;
    const int mblk = blockIdx.y * 256;
    const int nblk = blockIdx.x * 128;
    const int sub = lane >> 3, ri = lane & 7;

    float acc[4][8][4];
#pragma unroll
    for (int a = 0; a < 4; a++)
#pragma unroll
        for (int b = 0; b < 8; b++)
#pragma unroll
            for (int c = 0; c < 4; c++) acc[a][b][c] = 0.f;

    for (int kb = 0; kb < 1024; kb += 32) {
        __syncthreads();
#pragma unroll
        for (int i = 0; i < 6; i++) {
            int v = tid + i * 256;
            if (v < 1024) {
                int m = v >> 2, cv = v & 3;
                int gm = mblk + m;
                int col = kb + cv * 8;
                size_t byteoff = (size_t)((gm >> 5) + 1) * 65536 +
                                 (size_t)(col >> 9) * 32768 +
                                 SWZ((uint32_t)((gm & 31) * 1024 + (col & 511) * 2));
                *(uint4*)&As[m * 40 + cv * 8] = *(const uint4*)((const char*)g_outs + byteoff);
            } else {
                int u = v - 1024;
                int n = u >> 2, cv = u & 3;
                *(uint4*)&Ws[n * 40 + cv * 8] =
                    *(const uint4*)(W + (size_t)(nblk + n) * 1024 + kb + cv * 8);
            }
        }
        __syncthreads();
#pragma unroll
        for (int kk = 0; kk < 32; kk += 16) {
            uint32_t a[4][4], b[8][2];
#pragma unroll
            for (int mt = 0; mt < 4; mt++) {
                int row = wr * 64 + mt * 16 + (sub & 1) * 8 + ri;
                int col = kk + (sub >> 1) * 8;
                ldsm4(smem_u32(&As[row * 40 + col]), a[mt][0], a[mt][1], a[mt][2], a[mt][3]);
            }
#pragma unroll
            for (int ntp = 0; ntp < 4; ntp++) {
                int row = wc * 64 + ntp * 16 + (sub >> 1) * 8 + ri;
                int col = kk + (sub & 1) * 8;
                ldsm4(smem_u32(&Ws[row * 40 + col]),
                      b[ntp * 2][0], b[ntp * 2][1], b[ntp * 2 + 1][0], b[ntp * 2 + 1][1]);
            }
#pragma unroll
            for (int mt = 0; mt < 4; mt++)
#pragma unroll
                for (int nt = 0; nt < 8; nt++)
                    mma16816(acc[mt][nt], a[mt][0], a[mt][1], a[mt][2], a[mt][3],
                             b[nt][0], b[nt][1]);
        }
    }

    const int r0 = lane >> 2, c0 = (lane & 3) * 2;
#pragma unroll
    for (int mt = 0; mt < 4; mt++)
#pragma unroll
        for (int nt = 0; nt < 8; nt++) {
            int n = nblk + wc * 64 + nt * 8 + c0;
            float bv0 = bias[n], bv1 = bias[n + 1];
#pragma unroll
            for (int half = 0; half < 2; half++) {
                int m = mblk + wr * 64 + mt * 16 + r0 + half * 8;
                if (m < NSTEP * NB) {
                    int t = m >> 5, bb = m & 31;
                    size_t orow = (size_t)(bb * NSTEP + t) * VV;
                    out[orow + n]     = acc[mt][nt][half * 2 + 0] + bv0;
                    out[orow + n + 1] = acc[mt][nt][half * 2 + 1] + bv1;
                }
            }
        }
}

// ---------------- log_softmax: online single-read -----------------------------
__global__ void __launch_bounds__(256) k_lsm(float* __restrict__ out) {
    int row = blockIdx.x;
    float4* p = (float4*)(out + (size_t)row * VV);
    __shared__ float sm_m[256];
    __shared__ float sm_s[256];
    int tid = threadIdx.x;
    float m = -1e30f, s = 0.f;
    for (int i = tid; i < 8000; i += 256) {
        float4 v = p[i];
        float x[4] = {v.x, v.y, v.z, v.w};
#pragma unroll
        for (int k = 0; k < 4; k++) {
            float nm = fmaxf(m, x[k]);
            s = s * __expf(m - nm) + __expf(x[k] - nm);
            m = nm;
        }
    }
    sm_m[tid] = m; sm_s[tid] = s;
    __syncthreads();
    for (int st = 128; st; st >>= 1) {
        if (tid < st) {
            float m2 = sm_m[tid + st], s2 = sm_s[tid + st];
            float nm = fmaxf(sm_m[tid], m2);
            sm_s[tid] = sm_s[tid] * __expf(sm_m[tid] - nm) + s2 * __expf(m2 - nm);
            sm_m[tid] = nm;
        }
        __syncthreads();
    }
    float lse = sm_m[0] + logf(sm_s[0]);
    for (int i = tid; i < 8000; i += 256) {
        float4 v = p[i];
        v.x -= lse; v.y -= lse; v.z -= lse; v.w -= lse;
        p[i] = v;
    }
}

// ---------------- host ---------------------------------------------------------
static void* sym(const void* s) {
    void* p = nullptr;
    cudaGetSymbolAddress(&p, s);
    return p;
}

extern "C" void kernel_launch(void* const* d_in, const int* in_sizes, int n_in,
                              void* d_out, int out_size) {
    const int*   x     = (const int*)d_in[0];
    const float* h0in  = (const float*)d_in[1];
    const float* c0in  = (const float*)d_in[2];
    const float* x_enc = (const float*)d_in[3];
    const float* emb   = (const float*)d_in[4];
    const float* Wih0  = (const float*)d_in[5];
    const float* Whh0  = (const float*)d_in[6];
    const float* bih0  = (const float*)d_in[7];
    const float* bhh0  = (const float*)d_in[8];
    const float* Wih1  = (const float*)d_in[9];
    const float* Whh1  = (const float*)d_in[10];
    const float* bih1  = (const float*)d_in[11];
    const float* bhh1  = (const float*)d_in[12];
    const float* Wa    = (const float*)d_in[13];
    const float* ba    = (const float*)d_in[14];
    const float* Wl    = (const float*)d_in[15];
    const float* bl    = (const float*)d_in[16];
    const float* Wg    = (const float*)d_in[17];
    const float* bg    = (const float*)d_in[18];
    float* out = (float*)d_out;

    bf16*  pW0e = (bf16*)sym(g_W0e);
    bf16*  pWg  = (bf16*)sym(g_Wg);
    bf16*  pEs  = (bf16*)sym(g_eseq);
    float* pEg  = (float*)sym(g_eg);
    float* pB0i = (float*)sym(g_b0i);

    static bool attr_done = false;
    if (!attr_done) {
        cudaFuncSetAttribute(k_recur, cudaFuncAttributeMaxDynamicSharedMemorySize,
                             SMEM_RECUR);
        attr_done = true;
    }

    // ---- precompute: exactly 4 launches before k_recur ----
    k_prep_w<<<4096, 256>>>(Wih0, Whh0, Wih1, Whh1, Wl, Wa, Wg, x_enc);      // 1
    k_prep_m<<<256, 256>>>(x, emb, h0in, c0in, ba, x_enc,
                           bih0, bhh0, bih1, bhh1);                           // 2
    k_gemm_big<<<dim3(32, 16), 256>>>(pEs, pW0e, pB0i, pEg, 4096, 512);       // 3
    k_gemm_x2<<<dim3(8, 16, 2), 256>>>();                                     // 4

    // ---- recurrence: ONE persistent kernel ----
    k_recur<<<GRID_P, 256, SMEM_RECUR>>>(bl);                                 // 5

    // ---- generator + log_softmax ----
    k_gen<<<dim3(250, 8), 256>>>(pWg, bg, out);
    k_lsm<<<NSTEP * NB, 256>>>(out);

    (void)in_sizes; (void)n_in; (void)out_size;
}

// round 11
// speedup vs baseline: 1.3919x; 1.0545x over previous
#include <cuda_runtime.h>
#include <cuda_bf16.h>
#include <cstdint>

typedef __nv_bfloat16 bf16;

#define NB 32
#define TT 64
#define NSTEP 63
#define HH 1024
#define VV 32000
#define GRID_P 128
#define NTH 512            // threads in persistent kernel (16 warps)

// swizzle for 1024-byte-stride rows (32x512 bf16 chunks)
__device__ __forceinline__ uint32_t SWZ(uint32_t off) {
    return off ^ (((off >> 10) & 7u) << 4);
}

// ---------------- static scratch --------------------------------------------
__device__ __align__(128) bf16 g_W0q[4096 * 2048];  // 128 tiles x 4 q x 32KB, SWZ
__device__ __align__(128) bf16 g_W1q[4096 * 2048];
__device__ __align__(128) bf16 g_Wlzq[1024 * 1024]; // 32 tiles x 2 q x 32KB, SWZ
__device__ __align__(128) bf16 g_W0e[4096 * 512];   // interleaved rows, linear
__device__ __align__(128) bf16 g_WaT[1024 * 1024];
__device__ __align__(128) bf16 g_Wlc[1024 * 1024];
__device__ __align__(128) bf16 g_Wg [32000 * 1024];
__device__ __align__(128) bf16 g_eseq[2048 * 512];
__device__ __align__(128) float g_eg [2048 * 4096]; // e@W0e^T + b0 (interleaved cols)
__device__ __align__(128) bf16 g_xe[2048 * 1024];
__device__ __align__(128) bf16 g_xa[2048 * 1024];
__device__ __align__(128) bf16 g_xc[2048 * 1024];
// outs: 65 slots of 64KB; slot = 2 chunks x (32 b x 512 cols) swizzled; slot0 zeros
__device__ __align__(128) bf16 g_outs[2080 * 1024];
__device__ float g_b1i[4096];
__device__ float g_b0i[4096];
__device__ __align__(128) bf16 g_h0buf[2 * NB * HH]; // two 64KB chunked+SWZ bufs
__device__ __align__(128) bf16 g_h1buf[2 * NB * HH];
__device__ float g_c0[NB * HH];
__device__ float g_c1[NB * HH];
__device__ float g_ctxl[NB * HH];
__device__ float g_wl[NB * HH];
__device__ float g_badot[2048];
__device__ unsigned int g_flags[GRID_P];
__device__ unsigned int g_gen2;

// ---------------- helpers ----------------------------------------------------
__device__ __forceinline__ uint32_t smem_u32(const void* p) {
    return (uint32_t)__cvta_generic_to_shared(p);
}
__device__ __forceinline__ void ldsm4(uint32_t addr, uint32_t& r0, uint32_t& r1,
                                      uint32_t& r2, uint32_t& r3) {
    asm volatile("ldmatrix.sync.aligned.m8n8.x4.shared.b16 {%0,%1,%2,%3}, [%4];"
                 : "=r"(r0), "=r"(r1), "=r"(r2), "=r"(r3) : "r"(addr));
}
__device__ __forceinline__ void mma16816(float* c, uint32_t a0, uint32_t a1,
                                         uint32_t a2, uint32_t a3,
                                         uint32_t b0, uint32_t b1) {
    asm volatile(
        "mma.sync.aligned.m16n8k16.row.col.f32.bf16.bf16.f32 "
        "{%0,%1,%2,%3},{%4,%5,%6,%7},{%8,%9},{%0,%1,%2,%3};"
        : "+f"(c[0]), "+f"(c[1]), "+f"(c[2]), "+f"(c[3])
        : "r"(a0), "r"(a1), "r"(a2), "r"(a3), "r"(b0), "r"(b1));
}
__device__ __forceinline__ float sigmoidf_(float x) { return 1.f / (1.f + expf(-x)); }
__device__ __forceinline__ uint4 pack8(float4 a, float4 b) {
    uint4 o;
    __nv_bfloat162 p;
    p = __floats2bfloat162_rn(a.x, a.y); o.x = *(uint32_t*)&p;
    p = __floats2bfloat162_rn(a.z, a.w); o.y = *(uint32_t*)&p;
    p = __floats2bfloat162_rn(b.x, b.y); o.z = *(uint32_t*)&p;
    p = __floats2bfloat162_rn(b.z, b.w); o.w = *(uint32_t*)&p;
    return o;
}
// --- 1D TMA bulk + mbarrier ---
__device__ __forceinline__ void tma1d(uint32_t dst, const void* src, uint32_t bytes,
                                      uint32_t mbar) {
    asm volatile(
        "cp.async.bulk.shared::cluster.global.mbarrier::complete_tx::bytes "
        "[%0], [%1], %2, [%3];"
        :: "r"(dst), "l"(src), "r"(bytes), "r"(mbar) : "memory");
}
__device__ __forceinline__ void mb_init(uint32_t mbar) {
    asm volatile("mbarrier.init.shared.b64 [%0], 1;" :: "r"(mbar) : "memory");
}
__device__ __forceinline__ void mb_expect(uint32_t mbar, uint32_t tx) {
    asm volatile("mbarrier.arrive.expect_tx.shared.b64 _, [%0], %1;"
                 :: "r"(mbar), "r"(tx) : "memory");
}
__device__ __forceinline__ void mb_wait(uint32_t mbar, int parity) {
    asm volatile(
        "{\n\t.reg .pred P;\n"
        "WL%=:\n\t"
        "mbarrier.try_wait.parity.acquire.cta.shared::cta.b64 P, [%0], %1, 0x989680;\n\t"
        "@P bra WD%=;\n\t"
        "bra WL%=;\n"
        "WD%=:\n\t}"
        :: "r"(mbar), "r"(parity) : "memory");
}
// ---- contention-free grid barrier ----
__device__ __forceinline__ void gbar(unsigned int& gen) {
    gen++;
    __syncthreads();
    const int tid = threadIdx.x;
    const int bid = blockIdx.x;
    if (bid == 0) {
        if (tid == 0) {
            __threadfence();
            asm volatile("st.release.gpu.global.u32 [%0], %1;"
                         :: "l"(&g_flags[0]), "r"(gen) : "memory");
        }
        if (tid < GRID_P) {
            unsigned int v;
            do {
                __nanosleep(20);
                asm volatile("ld.acquire.gpu.global.u32 %0, [%1];"
                             : "=r"(v) : "l"(&g_flags[tid]));
            } while (v < gen);
        }
        __syncthreads();
        if (tid == 0) {
            asm volatile("st.release.gpu.global.u32 [%0], %1;"
                         :: "l"(&g_gen2), "r"(gen) : "memory");
        }
    } else {
        if (tid == 0) {
            __threadfence();
            asm volatile("st.release.gpu.global.u32 [%0], %1;"
                         :: "l"(&g_flags[bid]), "r"(gen) : "memory");
            unsigned int v;
            do {
                __nanosleep(20);
                asm volatile("ld.acquire.gpu.global.u32 %0, [%1];"
                             : "=r"(v) : "l"(&g_gen2));
            } while (v < gen);
        }
        __syncthreads();
    }
}

// ---------------- fused precompute kernel A: all weight conversions ----------
__global__ void k_prep_w(const float* __restrict__ Wih0, const float* __restrict__ Whh0,
                         const float* __restrict__ Wih1, const float* __restrict__ Whh1,
                         const float* __restrict__ Wl, const float* __restrict__ Wa,
                         const float* __restrict__ Wg, const float* __restrict__ x_enc) {
    const int stride = gridDim.x * blockDim.x;
    const int tid0 = blockIdx.x * blockDim.x + threadIdx.x;

    for (int i = tid0; i < 4096 * 256; i += stride) {
        int rn = i >> 8, c = (i & 255) * 8;
        int srow = (rn & 3) * 1024 + (rn >> 2);
        const float* s = (c < 1024) ? (Wih0 + (size_t)srow * 1536 + 512 + c)
                                    : (Whh0 + (size_t)srow * 1024 + (c - 1024));
        uint32_t off = SWZ((uint32_t)((rn & 31) * 1024 + (c & 511) * 2));
        char* d = (char*)g_W0q + (size_t)(rn >> 5) * 131072 + (size_t)(c >> 9) * 32768 + off;
        *(uint4*)d = pack8(((const float4*)s)[0], ((const float4*)s)[1]);
    }
    for (int i = tid0; i < 4096 * 256; i += stride) {
        int rn = i >> 8, c = (i & 255) * 8;
        int srow = (rn & 3) * 1024 + (rn >> 2);
        const float* s = (c < 1024) ? (Wih1 + (size_t)srow * 1024 + c)
                                    : (Whh1 + (size_t)srow * 1024 + (c - 1024));
        uint32_t off = SWZ((uint32_t)((rn & 31) * 1024 + (c & 511) * 2));
        char* d = (char*)g_W1q + (size_t)(rn >> 5) * 131072 + (size_t)(c >> 9) * 32768 + off;
        *(uint4*)d = pack8(((const float4*)s)[0], ((const float4*)s)[1]);
    }
    for (int i = tid0; i < 1024 * 128; i += stride) {
        int rn = i >> 7, c = (i & 127) * 8;
        const float* s = Wl + (size_t)rn * 2048 + c;
        uint32_t off = SWZ((uint32_t)((rn & 31) * 1024 + (c & 511) * 2));
        char* d = (char*)g_Wlzq + (size_t)(rn >> 5) * 65536 + (size_t)(c >> 9) * 32768 + off;
        *(uint4*)d = pack8(((const float4*)s)[0], ((const float4*)s)[1]);
    }
    for (int i = tid0; i < 4096 * 64; i += stride) {
        int rn = i >> 6, c8 = (i & 63) * 8;
        int srow = (rn & 3) * 1024 + (rn >> 2);
        const float* s = Wih0 + (size_t)srow * 1536 + c8;
        ((uint4*)g_W0e)[i] = pack8(((const float4*)s)[0], ((const float4*)s)[1]);
    }
    for (int i = tid0; i < 1024 * 1024; i += stride) {
        int n = i >> 10, h = i & 1023;
        g_WaT[i] = __float2bfloat16(Wa[h * 1024 + n]);
    }
    for (int i = tid0; i < 1024 * 128; i += stride) {
        int r = i >> 7, c8 = (i & 127) * 8;
        const float* s = Wl + (size_t)r * 2048 + 1024 + c8;
        ((uint4*)g_Wlc)[i] = pack8(((const float4*)s)[0], ((const float4*)s)[1]);
    }
    for (int i = tid0; i < 32000 * 128; i += stride) {
        const float4* s = (const float4*)Wg + (size_t)i * 2;
        ((uint4*)g_Wg)[i] = pack8(s[0], s[1]);
    }
    for (int i = tid0; i < 2048 * 128; i += stride) {
        const float4* s = (const float4*)x_enc + (size_t)i * 2;
        ((uint4*)g_xe)[i] = pack8(s[0], s[1]);
    }
}

// ---------------- fused precompute kernel B ----------------------------------
__global__ void k_prep_m(const int* __restrict__ x, const float* __restrict__ emb,
                         const float* __restrict__ h0in, const float* __restrict__ c0in,
                         const float* __restrict__ ba, const float* __restrict__ x_enc,
                         const float* __restrict__ bih0, const float* __restrict__ bhh0,
                         const float* __restrict__ bih1, const float* __restrict__ bhh1) {
    const int stride = gridDim.x * blockDim.x;
    const int tid0 = blockIdx.x * blockDim.x + threadIdx.x;

    for (int i = tid0; i < NSTEP * NB * 64; i += stride) {
        int c8 = (i & 63) * 8;
        int m = i >> 6;
        int b = m & 31, t = m >> 5;
        int tok = x[b * TT + t];
        const float* s = emb + (size_t)tok * 512 + c8;
        ((uint4*)g_eseq)[i] = pack8(((const float4*)s)[0], ((const float4*)s)[1]);
    }
    for (int i = tid0; i < NB * HH; i += stride) {
        int b = i >> 10, u = i & 1023;
        uint32_t off = (uint32_t)(u >> 9) * 32768 + SWZ((uint32_t)(b * 1024 + (u & 511) * 2));
        *(bf16*)((char*)g_h0buf + off) = __float2bfloat16(h0in[i]);
        *(bf16*)((char*)g_h1buf + off) = __float2bfloat16(h0in[NB * HH + i]);
        g_c0[i] = c0in[i];
        g_c1[i] = c0in[NB * HH + i];
    }
    for (int i = tid0; i < 4096; i += stride) {
        int u = i >> 2, g = i & 3;
        g_b0i[i] = bih0[g * 1024 + u] + bhh0[g * 1024 + u];
        g_b1i[i] = bih1[g * 1024 + u] + bhh1[g * 1024 + u];
    }
    {
        int gw = tid0 >> 5, lane = threadIdx.x & 31;
        int nw = stride >> 5;
        for (int row = gw; row < 2048; row += nw) {
            const float* xr = x_enc + (size_t)row * 1024;
            float s = 0.f;
            for (int h = lane; h < 1024; h += 32) s += ba[h] * xr[h];
#pragma unroll
            for (int o = 16; o; o >>= 1) s += __shfl_xor_sync(0xffffffffu, s, o);
            if (lane == 0) g_badot[row] = s;
        }
    }
}

// ---------------- generic 128x128 GEMM (eg precompute) -----------------------
__global__ void __launch_bounds__(256) k_gemm_big(
    const bf16* __restrict__ A, const bf16* __restrict__ W,
    const float* __restrict__ bias, float* __restrict__ Cf,
    int N, int K)
{
    __shared__ __align__(16) bf16 As[128 * 40];
    __shared__ __align__(16) bf16 Bs[128 * 40];
    const int tid = threadIdx.x, warp = tid >> 5, lane = tid & 31;
    const int wr = warp >> 2, wc = warp & 3;
    const int mblk = blockIdx.y * 128;
    const int nblk = blockIdx.x * 128;
    const int sub = lane >> 3, ri = lane & 7;

    float acc[4][4][4];
#pragma unroll
    for (int a = 0; a < 4; a++)
#pragma unroll
        for (int b = 0; b < 4; b++)
#pragma unroll
            for (int c = 0; c < 4; c++) acc[a][b][c] = 0.f;

    for (int kb = 0; kb < K; kb += 32) {
        __syncthreads();
#pragma unroll
        for (int i = 0; i < 4; i++) {
            int v = tid + i * 256;
            if (v < 512) {
                int m = v >> 2, cv = v & 3;
                *(uint4*)&As[m * 40 + cv * 8] =
                    *(const uint4*)(A + (size_t)(mblk + m) * K + kb + cv * 8);
            } else {
                int u = v - 512;
                int n = u >> 2, cv = u & 3;
                *(uint4*)&Bs[n * 40 + cv * 8] =
                    *(const uint4*)(W + (size_t)(nblk + n) * K + kb + cv * 8);
            }
        }
        __syncthreads();
#pragma unroll
        for (int kk = 0; kk < 32; kk += 16) {
            uint32_t a[4][4], b[4][2];
#pragma unroll
            for (int mt = 0; mt < 4; mt++) {
                int row = wr * 64 + mt * 16 + (sub & 1) * 8 + ri;
                int col = kk + (sub >> 1) * 8;
                ldsm4(smem_u32(&As[row * 40 + col]), a[mt][0], a[mt][1], a[mt][2], a[mt][3]);
            }
#pragma unroll
            for (int ntp = 0; ntp < 2; ntp++) {
                int row = wc * 32 + ntp * 16 + (sub >> 1) * 8 + ri;
                int col = kk + (sub & 1) * 8;
                ldsm4(smem_u32(&Bs[row * 40 + col]),
                      b[ntp * 2][0], b[ntp * 2][1], b[ntp * 2 + 1][0], b[ntp * 2 + 1][1]);
            }
#pragma unroll
            for (int mt = 0; mt < 4; mt++)
#pragma unroll
                for (int nt = 0; nt < 4; nt++)
                    mma16816(acc[mt][nt], a[mt][0], a[mt][1], a[mt][2], a[mt][3],
                             b[nt][0], b[nt][1]);
        }
    }

    const int r0 = lane >> 2, c0 = (lane & 3) * 2;
#pragma unroll
    for (int mt = 0; mt < 4; mt++)
#pragma unroll
        for (int nt = 0; nt < 4; nt++) {
            int n = nblk + wc * 32 + nt * 8 + c0;
#pragma unroll
            for (int half = 0; half < 2; half++) {
                int m = mblk + wr * 64 + mt * 16 + r0 + half * 8;
                Cf[(size_t)m * N + n]     = acc[mt][nt][half * 2 + 0] + bias[n];
                Cf[(size_t)m * N + n + 1] = acc[mt][nt][half * 2 + 1] + bias[n + 1];
            }
        }
}

// ---------------- fused xa/xc GEMM -------------------------------------------
__global__ void __launch_bounds__(256) k_gemm_x2() {
    const bf16* A = g_xe;
    const bf16* W = (blockIdx.z == 0) ? g_WaT : g_Wlc;
    bf16* Cb      = (blockIdx.z == 0) ? g_xa : g_xc;
    const int K = 1024, N = 1024;

    __shared__ __align__(16) bf16 As[128 * 40];
    __shared__ __align__(16) bf16 Bs[128 * 40];
    const int tid = threadIdx.x, warp = tid >> 5, lane = tid & 31;
    const int wr = warp >> 2, wc = warp & 3;
    const int mblk = blockIdx.y * 128;
    const int nblk = blockIdx.x * 128;
    const int sub = lane >> 3, ri = lane & 7;

    float acc[4][4][4];
#pragma unroll
    for (int a = 0; a < 4; a++)
#pragma unroll
        for (int b = 0; b < 4; b++)
#pragma unroll
            for (int c = 0; c < 4; c++) acc[a][b][c] = 0.f;

    for (int kb = 0; kb < K; kb += 32) {
        __syncthreads();
#pragma unroll
        for (int i = 0; i < 4; i++) {
            int v = tid + i * 256;
            if (v < 512) {
                int m = v >> 2, cv = v & 3;
                *(uint4*)&As[m * 40 + cv * 8] =
                    *(const uint4*)(A + (size_t)(mblk + m) * K + kb + cv * 8);
            } else {
                int u = v - 512;
                int n = u >> 2, cv = u & 3;
                *(uint4*)&Bs[n * 40 + cv * 8] =
                    *(const uint4*)(W + (size_t)(nblk + n) * K + kb + cv * 8);
            }
        }
        __syncthreads();
#pragma unroll
        for (int kk = 0; kk < 32; kk += 16) {
            uint32_t a[4][4], b[4][2];
#pragma unroll
            for (int mt = 0; mt < 4; mt++) {
                int row = wr * 64 + mt * 16 + (sub & 1) * 8 + ri;
                int col = kk + (sub >> 1) * 8;
                ldsm4(smem_u32(&As[row * 40 + col]), a[mt][0], a[mt][1], a[mt][2], a[mt][3]);
            }
#pragma unroll
            for (int ntp = 0; ntp < 2; ntp++) {
                int row = wc * 32 + ntp * 16 + (sub >> 1) * 8 + ri;
                int col = kk + (sub & 1) * 8;
                ldsm4(smem_u32(&Bs[row * 40 + col]),
                      b[ntp * 2][0], b[ntp * 2][1], b[ntp * 2 + 1][0], b[ntp * 2 + 1][1]);
            }
#pragma unroll
            for (int mt = 0; mt < 4; mt++)
#pragma unroll
                for (int nt = 0; nt < 4; nt++)
                    mma16816(acc[mt][nt], a[mt][0], a[mt][1], a[mt][2], a[mt][3],
                             b[nt][0], b[nt][1]);
        }
    }

    const int r0 = lane >> 2, c0 = (lane & 3) * 2;
#pragma unroll
    for (int mt = 0; mt < 4; mt++)
#pragma unroll
        for (int nt = 0; nt < 4; nt++) {
            int n = nblk + wc * 32 + nt * 8 + c0;
#pragma unroll
            for (int half = 0; half < 2; half++) {
                int m = mblk + wr * 64 + mt * 16 + r0 + half * 8;
                Cb[(size_t)m * N + n]     = __float2bfloat16(acc[mt][nt][half * 2 + 0]);
                Cb[(size_t)m * N + n + 1] = __float2bfloat16(acc[mt][nt][half * 2 + 1]);
            }
        }
}

// ---------------- persistent recurrence: TMA-fed, 16 warps -------------------
// smem: A0 @0, W0 @32768, A1 @65536, W1 @98304, red @131072 (67584), mb @198656
#define SMOFF_A0  0
#define SMOFF_W0  32768
#define SMOFF_A1  65536
#define SMOFF_W1  98304
#define SMOFF_RED 131072
#define SMOFF_MB  198656
#define SMEM_RECUR 198688

// 16 warps: warp w handles cols [w*32, w*32+32) of the 512-col chunk (2 kk iters)
__device__ __forceinline__ void comp_chunk(uint32_t aB, uint32_t wB,
                                           float acc[2][4][4]) {
    const int warp = threadIdx.x >> 5, lane = threadIdx.x & 31;
    const int sub = lane >> 3, ri = lane & 7;
#pragma unroll
    for (int kk = 0; kk < 32; kk += 16) {
        int col = (warp << 5) + kk;
        uint32_t a[2][4], b[4][2];
#pragma unroll
        for (int mt = 0; mt < 2; mt++) {
            uint32_t off = (uint32_t)((mt * 16 + (sub & 1) * 8 + ri) * 1024 +
                                      (col + (sub >> 1) * 8) * 2);
            ldsm4(aB + SWZ(off), a[mt][0], a[mt][1], a[mt][2], a[mt][3]);
        }
#pragma unroll
        for (int ntp = 0; ntp < 2; ntp++) {
            uint32_t off = (uint32_t)((ntp * 16 + (sub >> 1) * 8 + ri) * 1024 +
                                      (col + (sub & 1) * 8) * 2);
            ldsm4(wB + SWZ(off), b[ntp * 2][0], b[ntp * 2][1],
                  b[ntp * 2 + 1][0], b[ntp * 2 + 1][1]);
        }
#pragma unroll
        for (int mt = 0; mt < 2; mt++)
#pragma unroll
            for (int nt = 0; nt < 4; nt++)
                mma16816(acc[mt][nt], a[mt][0], a[mt][1], a[mt][2], a[mt][3],
                         b[nt][0], b[nt][1]);
    }
}

// reduce 16 warp-partials; result valid for tid < 256 (b = tid>>3, ul = tid&7)
__device__ __forceinline__ void reduce32(char* sm, float acc[2][4][4], float out[4]) {
    float* red = (float*)(sm + SMOFF_RED);
    const int tid = threadIdx.x, warp = tid >> 5, lane = tid & 31;
    __syncthreads();
    float* rw = red + warp * (32 * 33);
#pragma unroll
    for (int mt = 0; mt < 2; mt++)
#pragma unroll
        for (int nt = 0; nt < 4; nt++) {
            int m = mt * 16 + (lane >> 2);
            int n0 = nt * 8 + (lane & 3) * 2;
            rw[m * 33 + n0]           = acc[mt][nt][0];
            rw[m * 33 + n0 + 1]       = acc[mt][nt][1];
            rw[(m + 8) * 33 + n0]     = acc[mt][nt][2];
            rw[(m + 8) * 33 + n0 + 1] = acc[mt][nt][3];
        }
    __syncthreads();
    if (tid < 256) {
        int b = tid >> 3, ul = tid & 7;
#pragma unroll
        for (int g = 0; g < 4; g++) {
            float s = 0.f;
#pragma unroll
            for (int w = 0; w < 16; w++) s += red[w * (32 * 33) + b * 33 + ul * 4 + g];
            out[g] = s;
        }
    }
}

// C[32,32] = A[32, nch*512] @ Wtile^T. Double-buffered TMA pipeline.
__device__ void gemm32t(const char* a0, const char* a1, const char* a2, const char* a3,
                        const char* wtile, int nch, char* sm, int2& ph, float out[4]) {
    const int tid = threadIdx.x;
    const char* ach[4] = {a0, a1, a2, a3};
    uint32_t smb = smem_u32(sm);
    uint32_t mb0 = smb + SMOFF_MB, mb1 = smb + SMOFF_MB + 8;
    float acc[2][4][4];
#pragma unroll
    for (int a = 0; a < 2; a++)
#pragma unroll
        for (int b = 0; b < 4; b++)
#pragma unroll
            for (int c = 0; c < 4; c++) acc[a][b][c] = 0.f;

    if (tid == 0) {
        mb_expect(mb0, 65536);
        tma1d(smb + SMOFF_A0, ach[0], 32768, mb0);
        tma1d(smb + SMOFF_W0, wtile, 32768, mb0);
    }
    for (int ch = 0; ch < nch; ch++) {
        int buf = ch & 1;
        if (ch + 1 < nch && tid == 0) {
            uint32_t mbn = buf ? mb0 : mb1;
            mb_expect(mbn, 65536);
            tma1d(smb + (buf ? SMOFF_A0 : SMOFF_A1), ach[ch + 1], 32768, mbn);
            tma1d(smb + (buf ? SMOFF_W0 : SMOFF_W1),
                  wtile + (size_t)(ch + 1) * 32768, 32768, mbn);
        }
        if (buf) { mb_wait(mb1, ph.y); ph.y ^= 1; }
        else     { mb_wait(mb0, ph.x); ph.x ^= 1; }
        comp_chunk(smb + (buf ? SMOFF_A1 : SMOFF_A0),
                   smb + (buf ? SMOFF_W1 : SMOFF_W0), acc);
        __syncthreads();
    }
    reduce32(sm, acc, out);
}

// ---------------- attention (device func, 512 threads) -----------------------
__device__ void attn_dev(int b, const char* __restrict__ h1base, char* smraw) {
    float* h1s = (float*)(smraw + SMOFF_RED);
    float* sc = h1s + 1024;
    int tid = threadIdx.x;
    for (int u = tid; u < 1024; u += NTH) {
        uint32_t off = (uint32_t)(u >> 9) * 32768 + SWZ((uint32_t)(b * 1024 + (u & 511) * 2));
        h1s[u] = __bfloat162float(*(const bf16*)(h1base + off));
    }
    __syncthreads();
    int warp = tid >> 5, lane = tid & 31;
#pragma unroll
    for (int jj = 0; jj < 4; jj++) {
        int j = warp * 4 + jj;
        const uint4* xr = (const uint4*)(g_xa + (size_t)(b * 64 + j) * 1024);
        float s = 0.f;
        for (int k4 = lane; k4 < 128; k4 += 32) {
            uint4 v = xr[k4];
            const __nv_bfloat162* p2 = (const __nv_bfloat162*)&v;
            int base = k4 * 8;
#pragma unroll
            for (int q = 0; q < 4; q++) {
                float2 f = __bfloat1622float2(p2[q]);
                s += h1s[base + q * 2] * f.x + h1s[base + q * 2 + 1] * f.y;
            }
        }
#pragma unroll
        for (int o = 16; o; o >>= 1) s += __shfl_xor_sync(0xffffffffu, s, o);
        if (lane == 0) sc[j] = s + g_badot[b * 64 + j];
    }
    __syncthreads();
    if (warp == 0) {
        float v0 = sc[lane], v1 = sc[lane + 32];
        float m = fmaxf(v0, v1);
#pragma unroll
        for (int o = 16; o; o >>= 1) m = fmaxf(m, __shfl_xor_sync(0xffffffffu, m, o));
        float e0 = expf(v0 - m), e1 = expf(v1 - m);
        float s = e0 + e1;
#pragma unroll
        for (int o = 16; o; o >>= 1) s += __shfl_xor_sync(0xffffffffu, s, o);
        sc[lane] = e0 / s;
        sc[lane + 32] = e1 / s;
    }
    __syncthreads();
    {
        int n0 = tid * 2;
        float a0 = 0.f, a1 = 0.f;
        const char* base = (const char*)g_xc + (size_t)b * 131072 + n0 * 2;
#pragma unroll 8
        for (int j = 0; j < 64; j++) {
            uint32_t v = *(const uint32_t*)(base + (size_t)j * 2048);
            float2 f0 = __bfloat1622float2(*(__nv_bfloat162*)&v);
            float w = sc[j];
            a0 += w * f0.x; a1 += w * f0.y;
        }
        *(float2*)&g_ctxl[b * 1024 + n0] = make_float2(a0, a1);
    }
}

// ---------------- persistent recurrence kernel -------------------------------
__global__ void __launch_bounds__(NTH) k_recur(const float* __restrict__ bl) {
    extern __shared__ __align__(128) char smraw[];
    const int bid = blockIdx.x;
    const int tid = threadIdx.x;

    if (tid == 0) {
        mb_init(smem_u32(smraw) + SMOFF_MB);
        mb_init(smem_u32(smraw) + SMOFF_MB + 8);
    }
    asm volatile("fence.proxy.async.shared::cta;" ::: "memory");
    __syncthreads();
    int2 ph = make_int2(0, 0);
    unsigned int gen;
    asm volatile("ld.acquire.gpu.global.u32 %0, [%1];" : "=r"(gen) : "l"(&g_gen2));

    for (int t = 0; t < NSTEP; t++) {
        const char* h0_in  = (const char*)g_h0buf + (t & 1) * 65536;
        char*       h0_out = (char*)g_h0buf + ((t + 1) & 1) * 65536;
        const char* h1_in  = (const char*)g_h1buf + (t & 1) * 65536;
        char*       h1_out = (char*)g_h1buf + ((t + 1) & 1) * 65536;
        const char* prev   = (const char*)g_outs + (size_t)t * 65536;

        // P1: layer-0 gates + cell
        {
            float s[4];
            gemm32t(prev, prev + 32768, h0_in, h0_in + 32768,
                    (const char*)g_W0q + (size_t)bid * 131072, 4, smraw, ph, s);
            if (tid < 256) {
                const float* egp = g_eg + (size_t)t * 32 * 4096;
                int b = tid >> 3, ul = tid & 7;
                int rn = bid * 32 + ul * 4;
                int u = rn >> 2;
                float ig = s[0] + egp[b * 4096 + rn];
                float fg = s[1] + egp[b * 4096 + rn + 1];
                float gg = s[2] + egp[b * 4096 + rn + 2];
                float og = s[3] + egp[b * 4096 + rn + 3];
                float cn = sigmoidf_(fg) * g_c0[b * 1024 + u] + sigmoidf_(ig) * tanhf(gg);
                g_c0[b * 1024 + u] = cn;
                uint32_t off = (uint32_t)(u >> 9) * 32768 +
                               SWZ((uint32_t)(b * 1024 + (u & 511) * 2));
                *(bf16*)(h0_out + off) = __float2bfloat16(sigmoidf_(og) * tanhf(cn));
            }
        }
        gbar(gen);

        // P2: layer-1 gates + cell
        {
            float s[4];
            gemm32t(h0_out, h0_out + 32768, h1_in, h1_in + 32768,
                    (const char*)g_W1q + (size_t)bid * 131072, 4, smraw, ph, s);
            if (tid < 256) {
                int b = tid >> 3, ul = tid & 7;
                int rn = bid * 32 + ul * 4;
                int u = rn >> 2;
                float ig = s[0] + g_b1i[rn];
                float fg = s[1] + g_b1i[rn + 1];
                float gg = s[2] + g_b1i[rn + 2];
                float og = s[3] + g_b1i[rn + 3];
                float cn = sigmoidf_(fg) * g_c1[b * 1024 + u] + sigmoidf_(ig) * tanhf(gg);
                g_c1[b * 1024 + u] = cn;
                uint32_t off = (uint32_t)(u >> 9) * 32768 +
                               SWZ((uint32_t)(b * 1024 + (u & 511) * 2));
                *(bf16*)(h1_out + off) = __float2bfloat16(sigmoidf_(og) * tanhf(cn));
            }
        }
        gbar(gen);

        // P3: attention (blocks 0-31) || z @ Wlz^T (blocks 32-63)
        if (bid < 32) {
            attn_dev(bid, h1_out, smraw);
        } else if (bid < 64) {
            float s[4];
            gemm32t(h1_out, h1_out + 32768, h1_out, h1_out,
                    (const char*)g_Wlzq + (size_t)(bid - 32) * 65536, 2, smraw, ph, s);
            if (tid < 256) {
                int b = tid >> 3, ul = tid & 7;
                int n = (bid - 32) * 32 + ul * 4;
#pragma unroll
                for (int g = 0; g < 4; g++) g_wl[b * 1024 + n + g] = s[g];
            }
        }
        gbar(gen);

        // P4: out = tanh(wl + bl + ctx) -> outs slot t+1 (chunked + SWZ)
        if (bid < 32) {
            char* outt = (char*)g_outs + (size_t)(t + 1) * 65536;
#pragma unroll
            for (int j = 0; j < 2; j++) {
                int n = tid * 2 + j;
                float v = g_wl[bid * 1024 + n] + bl[n] + g_ctxl[bid * 1024 + n];
                uint32_t off = (uint32_t)(n >> 9) * 32768 +
                               SWZ((uint32_t)(bid * 1024 + (n & 511) * 2));
                *(bf16*)(outt + off) = __float2bfloat16(tanhf(v));
            }
        }
        gbar(gen);
    }
}

// ---------------- generator GEMM 256x128 tiles (A from chunked outs) ----------
__global__ void __launch_bounds__(256) k_gen(const bf16* __restrict__ W,
                                             const float* __restrict__ bias,
                                             float* __restrict__ out) {
    __shared__ __align__(16) bf16 As[256 * 40];
    __shared__ __align__(16) bf16 Ws[128 * 40];
    const int tid = threadIdx.x, warp = tid >> 5, lane = tid & 31;
    const int wr = warp >> 1, wc = warp & 1;
    const int mblk = blockIdx.y * 256;
    const int nblk = blockIdx.x * 128;
    const int sub = lane >> 3, ri = lane & 7;

    float acc[4][8][4];
#pragma unroll
    for (int a = 0; a < 4; a++)
#pragma unroll
        for (int b = 0; b < 8; b++)
#pragma unroll
            for (int c = 0; c < 4; c++) acc[a][b][c] = 0.f;

    for (int kb = 0; kb < 1024; kb += 32) {
        __syncthreads();
#pragma unroll
        for (int i = 0; i < 6; i++) {
            int v = tid + i * 256;
            if (v < 1024) {
                int m = v >> 2, cv = v & 3;
                int gm = mblk + m;
                int col = kb + cv * 8;
                size_t byteoff = (size_t)((gm >> 5) + 1) * 65536 +
                                 (size_t)(col >> 9) * 32768 +
                                 SWZ((uint32_t)((gm & 31) * 1024 + (col & 511) * 2));
                *(uint4*)&As[m * 40 + cv * 8] = *(const uint4*)((const char*)g_outs + byteoff);
            } else {
                int u = v - 1024;
                int n = u >> 2, cv = u & 3;
                *(uint4*)&Ws[n * 40 + cv * 8] =
                    *(const uint4*)(W + (size_t)(nblk + n) * 1024 + kb + cv * 8);
            }
        }
        __syncthreads();
#pragma unroll
        for (int kk = 0; kk < 32; kk += 16) {
            uint32_t a[4][4], b[8][2];
#pragma unroll
            for (int mt = 0; mt < 4; mt++) {
                int row = wr * 64 + mt * 16 + (sub & 1) * 8 + ri;
                int col = kk + (sub >> 1) * 8;
                ldsm4(smem_u32(&As[row * 40 + col]), a[mt][0], a[mt][1], a[mt][2], a[mt][3]);
            }
#pragma unroll
            for (int ntp = 0; ntp < 4; ntp++) {
                int row = wc * 64 + ntp * 16 + (sub >> 1) * 8 + ri;
                int col = kk + (sub & 1) * 8;
                ldsm4(smem_u32(&Ws[row * 40 + col]),
                      b[ntp * 2][0], b[ntp * 2][1], b[ntp * 2 + 1][0], b[ntp * 2 + 1][1]);
            }
#pragma unroll
            for (int mt = 0; mt < 4; mt++)
#pragma unroll
                for (int nt = 0; nt < 8; nt++)
                    mma16816(acc[mt][nt], a[mt][0], a[mt][1], a[mt][2], a[mt][3],
                             b[nt][0], b[nt][1]);
        }
    }

    const int r0 = lane >> 2, c0 = (lane & 3) * 2;
#pragma unroll
    for (int mt = 0; mt < 4; mt++)
#pragma unroll
        for (int nt = 0; nt < 8; nt++) {
            int n = nblk + wc * 64 + nt * 8 + c0;
            float bv0 = bias[n], bv1 = bias[n + 1];
#pragma unroll
            for (int half = 0; half < 2; half++) {
                int m = mblk + wr * 64 + mt * 16 + r0 + half * 8;
                if (m < NSTEP * NB) {
                    int t = m >> 5, bb = m & 31;
                    size_t orow = (size_t)(bb * NSTEP + t) * VV;
                    out[orow + n]     = acc[mt][nt][half * 2 + 0] + bv0;
                    out[orow + n + 1] = acc[mt][nt][half * 2 + 1] + bv1;
                }
            }
        }
}

// ---------------- log_softmax: online single-read -----------------------------
__global__ void __launch_bounds__(256) k_lsm(float* __restrict__ out) {
    int row = blockIdx.x;
    float4* p = (float4*)(out + (size_t)row * VV);
    __shared__ float sm_m[256];
    __shared__ float sm_s[256];
    int tid = threadIdx.x;
    float m = -1e30f, s = 0.f;
    for (int i = tid; i < 8000; i += 256) {
        float4 v = p[i];
        float x[4] = {v.x, v.y, v.z, v.w};
#pragma unroll
        for (int k = 0; k < 4; k++) {
            float nm = fmaxf(m, x[k]);
            s = s * __expf(m - nm) + __expf(x[k] - nm);
            m = nm;
        }
    }
    sm_m[tid] = m; sm_s[tid] = s;
    __syncthreads();
    for (int st = 128; st; st >>= 1) {
        if (tid < st) {
            float m2 = sm_m[tid + st], s2 = sm_s[tid + st];
            float nm = fmaxf(sm_m[tid], m2);
            sm_s[tid] = sm_s[tid] * __expf(sm_m[tid] - nm) + s2 * __expf(m2 - nm);
            sm_m[tid] = nm;
        }
        __syncthreads();
    }
    float lse = sm_m[0] + logf(sm_s[0]);
    for (int i = tid; i < 8000; i += 256) {
        float4 v = p[i];
        v.x -= lse; v.y -= lse; v.z -= lse; v.w -= lse;
        p[i] = v;
    }
}

// ---------------- host ---------------------------------------------------------
static void* sym(const void* s) {
    void* p = nullptr;
    cudaGetSymbolAddress(&p, s);
    return p;
}

extern "C" void kernel_launch(void* const* d_in, const int* in_sizes, int n_in,
                              void* d_out, int out_size) {
    const int*   x     = (const int*)d_in[0];
    const float* h0in  = (const float*)d_in[1];
    const float* c0in  = (const float*)d_in[2];
    const float* x_enc = (const float*)d_in[3];
    const float* emb   = (const float*)d_in[4];
    const float* Wih0  = (const float*)d_in[5];
    const float* Whh0  = (const float*)d_in[6];
    const float* bih0  = (const float*)d_in[7];
    const float* bhh0  = (const float*)d_in[8];
    const float* Wih1  = (const float*)d_in[9];
    const float* Whh1  = (const float*)d_in[10];
    const float* bih1  = (const float*)d_in[11];
    const float* bhh1  = (const float*)d_in[12];
    const float* Wa    = (const float*)d_in[13];
    const float* ba    = (const float*)d_in[14];
    const float* Wl    = (const float*)d_in[15];
    const float* bl    = (const float*)d_in[16];
    const float* Wg    = (const float*)d_in[17];
    const float* bg    = (const float*)d_in[18];
    float* out = (float*)d_out;

    bf16*  pW0e = (bf16*)sym(g_W0e);
    bf16*  pWg  = (bf16*)sym(g_Wg);
    bf16*  pEs  = (bf16*)sym(g_eseq);
    float* pEg  = (float*)sym(g_eg);
    float* pB0i = (float*)sym(g_b0i);

    static bool attr_done = false;
    if (!attr_done) {
        cudaFuncSetAttribute(k_recur, cudaFuncAttributeMaxDynamicSharedMemorySize,
                             SMEM_RECUR);
        attr_done = true;
    }

    // ---- precompute ----
    k_prep_w<<<4096, 256>>>(Wih0, Whh0, Wih1, Whh1, Wl, Wa, Wg, x_enc);
    k_prep_m<<<256, 256>>>(x, emb, h0in, c0in, ba, x_enc,
                           bih0, bhh0, bih1, bhh1);
    k_gemm_big<<<dim3(32, 16), 256>>>(pEs, pW0e, pB0i, pEg, 4096, 512);
    k_gemm_x2<<<dim3(8, 16, 2), 256>>>();

    // ---- recurrence: ONE persistent kernel, 16 warps/CTA ----
    k_recur<<<GRID_P, NTH, SMEM_RECUR>>>(bl);

    // ---- generator + log_softmax ----
    k_gen<<<dim3(250, 8), 256>>>(pWg, bg, out);
    k_lsm<<<NSTEP * NB, 256>>>(out);

    (void)in_sizes; (void)n_in; (void)out_size;
}